// round 11
// baseline (speedup 1.0000x reference)
#include <cuda_runtime.h>
#include <cuda_bf16.h>
#include <math.h>
#include <stdint.h>

#define B 8
#define N 56
#define HW 3136           // 56*56
#define TOK 25088         // 8*56*56
#define EMBED 192
#define D1 576
#define TWO_N 112
#define RPE_H 32

// ---------------- device scratch ----------------
__device__ float g_p[TOK * D1];
__device__ float g_qv[TOK * D1];
__device__ float g_t[TOK * D1];
__device__ float g_a[2 * TWO_N * D1];   // a1 then a2
__device__ float g_h[2 * TWO_N * RPE_H];

__device__ __forceinline__ float silu_f(float x) {
    return __fdividef(x, 1.0f + __expf(-x));
}

__device__ __forceinline__ uint32_t to_tf32(float x) {
    uint32_t r;
    asm("cvt.rna.tf32.f32 %0, %1;" : "=r"(r) : "f"(x));
    return r;
}

__device__ __forceinline__ void mma_tf32(float c[4], const uint32_t a[4], const uint32_t b[2]) {
    asm volatile(
        "mma.sync.aligned.m16n8k8.row.col.f32.tf32.tf32.f32 "
        "{%0,%1,%2,%3}, {%4,%5,%6,%7}, {%8,%9}, {%0,%1,%2,%3};"
        : "+f"(c[0]), "+f"(c[1]), "+f"(c[2]), "+f"(c[3])
        : "r"(a[0]), "r"(a[1]), "r"(a[2]), "r"(a[3]), "r"(b[0]), "r"(b[1]));
}

// f32x2 packed helpers (sm_103a FFMA2 — PTX-only path)
__device__ __forceinline__ unsigned long long pk2(float lo, float hi) {
    unsigned long long r;
    asm("mov.b64 %0, {%1, %2};" : "=l"(r) : "f"(lo), "f"(hi));
    return r;
}
__device__ __forceinline__ void fma2(unsigned long long& c, unsigned long long a, unsigned long long b) {
    asm("fma.rn.f32x2 %0, %1, %2, %0;" : "+l"(c) : "l"(a), "l"(b));
}
__device__ __forceinline__ void unpk2(float& lo, float& hi, unsigned long long v) {
    asm("mov.b64 {%0, %1}, %2;" : "=f"(lo), "=f"(hi) : "l"(v));
}

// ---------------- kernel A1: RPE hidden layers ----------------
__global__ void rpe_hidden_kernel(const float* __restrict__ w0a, const float* __restrict__ b0a,
                                  const float* __restrict__ wsa, const float* __restrict__ bsa,
                                  const float* __restrict__ w0b, const float* __restrict__ b0b,
                                  const float* __restrict__ wsb, const float* __restrict__ bsb) {
    int t = threadIdx.x;
    int tno = t >> 7;
    int row = t & 127;
    if (row >= TWO_N) return;
    const float* W0 = tno ? w0b : w0a;
    const float* B0 = tno ? b0b : b0a;
    const float* WS = tno ? wsb : wsa;
    const float* BS = tno ? bsb : bsa;

    float tv;
    if (row == 0 || row == 56) tv = 0.0f;
    else if (row < 56) tv = (float)row;
    else tv = -(float)(row - 56);

    float h[RPE_H];
#pragma unroll
    for (int j = 0; j < RPE_H; j++) h[j] = tv * W0[j] + B0[j];

    for (int L = 0; L < 3; L++) {
        float hn[RPE_H];
#pragma unroll
        for (int j = 0; j < RPE_H; j++) {
            float s = BS[L * RPE_H + j];
#pragma unroll
            for (int k = 0; k < RPE_H; k++)
                s += fmaxf(h[k], 0.0f) * WS[L * RPE_H * RPE_H + j * RPE_H + k];
            hn[j] = s;
        }
#pragma unroll
        for (int j = 0; j < RPE_H; j++) h[j] = hn[j];
    }
#pragma unroll
    for (int k = 0; k < RPE_H; k++)
        g_h[(tno * TWO_N + row) * RPE_H + k] = fmaxf(h[k], 0.0f);
}

// ---------------- kernel A2: RPE output layer * decay ----------------
__global__ void rpe_out_kernel(const float* __restrict__ wo1, const float* __restrict__ bo1,
                               const float* __restrict__ wo2, const float* __restrict__ bo2,
                               const float* __restrict__ slope) {
    int bx = blockIdx.x;
    int tno = bx / TWO_N;
    int row = bx % TWO_N;
    const float* WO = tno ? wo2 : wo1;
    const float* BO = tno ? bo2 : bo1;

    __shared__ float hs[RPE_H];
    if (threadIdx.x < RPE_H)
        hs[threadIdx.x] = g_h[(tno * TWO_N + row) * RPE_H + threadIdx.x];
    __syncthreads();

    int e;
    if (row == 0 || row == 56) e = 0;
    else if (row < 56) e = row;
    else e = TWO_N - row;

    for (int d = threadIdx.x; d < D1; d += blockDim.x) {
        float s = BO[d];
#pragma unroll
        for (int k = 0; k < RPE_H; k++) s += hs[k] * WO[d * RPE_H + k];
        float sl = slope[d];
        sl = fminf(fmaxf(sl, 0.0f), 1.0f);
        sl = 0.95f + 0.05f * sl;
        float dec = (e == 0) ? 1.0f : __powf(sl, (float)e);
        g_a[(tno * TWO_N + row) * D1 + d] = s * dec;
    }
}

// ---------------- kernel B: fused p / q*v GEMMs (TF32 mma, 2-stage pipeline, BN=32) ----------------
#define APITCH 136   // ≡ 8 mod 32 -> conflict-free frag loads
#define BPITCH 40    // ≡ 8 mod 32
#define PQV_SMEM ((2 * 32 * APITCH + 2 * 3 * 32 * BPITCH) * 4)   // 65536 B

__global__ __launch_bounds__(256, 2) void pqv_kernel(
    const float* __restrict__ x,
    const float* __restrict__ pw, const float* __restrict__ pb,
    const float* __restrict__ qw, const float* __restrict__ qb,
    const float* __restrict__ vw, const float* __restrict__ vb) {
    extern __shared__ float smem[];
    float (*As)[32][APITCH]    = (float (*)[32][APITCH])smem;
    float (*Bs)[3][32][BPITCH] = (float (*)[3][32][BPITCH])(smem + 2 * 32 * APITCH);

    int tid = threadIdx.x;
    int warp = tid >> 5, lane = tid & 31;
    int wm = (warp >> 1) * 32;
    int wn = (warp & 1) * 16;
    int quad = lane >> 2, tid4 = lane & 3;
    int m0 = blockIdx.y * 128, n0 = blockIdx.x * 32;

    int lrow = tid >> 1;
    int lcb  = (tid & 1) * 16;
    int wrow = tid >> 3;
    int wkb  = (tid & 7) * 4;

    const float* wmats[3] = {pw, qw, vw};

    float c[3][2][2][4];
#pragma unroll
    for (int mt2 = 0; mt2 < 3; mt2++)
#pragma unroll
        for (int i = 0; i < 2; i++)
#pragma unroll
            for (int j = 0; j < 2; j++)
#pragma unroll
                for (int r = 0; r < 4; r++) c[mt2][i][j][r] = 0.0f;

    float4 pa[4];
    float4 pwv[3];

#pragma unroll
    for (int v = 0; v < 4; v++)
        pa[v] = *(const float4*)&x[(m0 + lrow) * EMBED + lcb + v * 4];
#pragma unroll
    for (int mat = 0; mat < 3; mat++)
        pwv[mat] = *(const float4*)&wmats[mat][(n0 + wrow) * EMBED + wkb];
    {
#pragma unroll
        for (int v = 0; v < 4; v++) {
            As[0][lcb + v * 4 + 0][lrow] = __uint_as_float(to_tf32(pa[v].x));
            As[0][lcb + v * 4 + 1][lrow] = __uint_as_float(to_tf32(pa[v].y));
            As[0][lcb + v * 4 + 2][lrow] = __uint_as_float(to_tf32(pa[v].z));
            As[0][lcb + v * 4 + 3][lrow] = __uint_as_float(to_tf32(pa[v].w));
        }
#pragma unroll
        for (int mat = 0; mat < 3; mat++) {
            Bs[0][mat][wkb + 0][wrow] = __uint_as_float(to_tf32(pwv[mat].x));
            Bs[0][mat][wkb + 1][wrow] = __uint_as_float(to_tf32(pwv[mat].y));
            Bs[0][mat][wkb + 2][wrow] = __uint_as_float(to_tf32(pwv[mat].z));
            Bs[0][mat][wkb + 3][wrow] = __uint_as_float(to_tf32(pwv[mat].w));
        }
    }
    __syncthreads();

    int s = 0;
    for (int kb = 0; kb < EMBED; kb += 32, s ^= 1) {
        bool hasNext = (kb + 32) < EMBED;
        if (hasNext) {
            int kn = kb + 32;
#pragma unroll
            for (int v = 0; v < 4; v++)
                pa[v] = *(const float4*)&x[(m0 + lrow) * EMBED + kn + lcb + v * 4];
#pragma unroll
            for (int mat = 0; mat < 3; mat++)
                pwv[mat] = *(const float4*)&wmats[mat][(n0 + wrow) * EMBED + kn + wkb];
        }

#pragma unroll
        for (int k8 = 0; k8 < 32; k8 += 8) {
            uint32_t a[2][4];
#pragma unroll
            for (int mt = 0; mt < 2; mt++) {
                int mb = wm + mt * 16;
                a[mt][0] = __float_as_uint(As[s][k8 + tid4][mb + quad]);
                a[mt][1] = __float_as_uint(As[s][k8 + tid4][mb + quad + 8]);
                a[mt][2] = __float_as_uint(As[s][k8 + tid4 + 4][mb + quad]);
                a[mt][3] = __float_as_uint(As[s][k8 + tid4 + 4][mb + quad + 8]);
            }
#pragma unroll
            for (int mat = 0; mat < 3; mat++) {
#pragma unroll
                for (int nt = 0; nt < 2; nt++) {
                    uint32_t b[2];
                    int nb = wn + nt * 8 + quad;
                    b[0] = __float_as_uint(Bs[s][mat][k8 + tid4][nb]);
                    b[1] = __float_as_uint(Bs[s][mat][k8 + tid4 + 4][nb]);
#pragma unroll
                    for (int mt = 0; mt < 2; mt++)
                        mma_tf32(c[mat][mt][nt], a[mt], b);
                }
            }
        }

        if (hasNext) {
            int ns = s ^ 1;
#pragma unroll
            for (int v = 0; v < 4; v++) {
                As[ns][lcb + v * 4 + 0][lrow] = __uint_as_float(to_tf32(pa[v].x));
                As[ns][lcb + v * 4 + 1][lrow] = __uint_as_float(to_tf32(pa[v].y));
                As[ns][lcb + v * 4 + 2][lrow] = __uint_as_float(to_tf32(pa[v].z));
                As[ns][lcb + v * 4 + 3][lrow] = __uint_as_float(to_tf32(pa[v].w));
            }
#pragma unroll
            for (int mat = 0; mat < 3; mat++) {
                Bs[ns][mat][wkb + 0][wrow] = __uint_as_float(to_tf32(pwv[mat].x));
                Bs[ns][mat][wkb + 1][wrow] = __uint_as_float(to_tf32(pwv[mat].y));
                Bs[ns][mat][wkb + 2][wrow] = __uint_as_float(to_tf32(pwv[mat].z));
                Bs[ns][mat][wkb + 3][wrow] = __uint_as_float(to_tf32(pwv[mat].w));
            }
        }
        __syncthreads();
    }

#pragma unroll
    for (int mt = 0; mt < 2; mt++) {
#pragma unroll
        for (int half = 0; half < 2; half++) {
            int m = m0 + wm + mt * 16 + quad + half * 8;
#pragma unroll
            for (int nt = 0; nt < 2; nt++) {
                int n = n0 + wn + nt * 8 + tid4 * 2;
                float cp0 = c[0][mt][nt][half * 2 + 0] + pb[n];
                float cp1 = c[0][mt][nt][half * 2 + 1] + pb[n + 1];
                float cq0 = c[1][mt][nt][half * 2 + 0] + qb[n];
                float cq1 = c[1][mt][nt][half * 2 + 1] + qb[n + 1];
                float cv0 = c[2][mt][nt][half * 2 + 0] + vb[n];
                float cv1 = c[2][mt][nt][half * 2 + 1] + vb[n + 1];
                float2 pv = make_float2(silu_f(cp0), silu_f(cp1));
                float2 qv = make_float2(silu_f(cq0) * silu_f(cv0),
                                        silu_f(cq1) * silu_f(cv1));
                *(float2*)&g_p[m * D1 + n] = pv;
                *(float2*)&g_qv[m * D1 + n] = qv;
            }
        }
    }
}

// ---------------- kernel C: axial Toeplitz + gate (f32x2, manual software pipeline) ----------------
// One block per (batch, 8-channel group). 512 threads: tid = (ti*8+tj)*8 + d.
// Iteration j+1's smem operands are prefetched into registers before iteration j's
// FMA2s consume the staged values — breaks the LDS->pack->FMA2 latency chain.
#define XPITCH 448
#define AELEN 112
__global__ __launch_bounds__(512, 1) void toeplitz_kernel() {
    extern __shared__ float sm[];
    float* Xs  = sm;
    float* a1e = sm + N * XPITCH;
    float* a2e = a1e + AELEN * 8;

    int dg = blockIdx.x;
    int b  = blockIdx.y;
    int dbase = dg * 8;
    int tid = threadIdx.x;

    for (int idx = tid; idx < HW * 2; idx += 512) {
        int pos = idx >> 1;
        int q = (idx & 1) * 4;
        float4 v = *(const float4*)&g_qv[(size_t)(b * HW + pos) * D1 + dbase + q];
        int i = pos / N, j = pos % N;
        *(float4*)&Xs[i * XPITCH + j * 8 + q] = v;
    }
    for (int idx = tid; idx < AELEN * 8; idx += 512) {
        int k = idx >> 3, dd = idx & 7;
        int src = (k + 57) % TWO_N;
        a1e[idx] = g_a[src * D1 + dbase + dd];
        a2e[idx] = g_a[TWO_N * D1 + src * D1 + dbase + dd];
    }
    __syncthreads();

    int d  = tid & 7;
    int tp = tid >> 3;
    int tj = tp & 7;
    int ti = tp >> 3;
    int i0 = ti * 7, j0 = tj * 7;

    unsigned long long acc[7][4];
#pragma unroll
    for (int ii = 0; ii < 7; ii++)
#pragma unroll
        for (int p = 0; p < 4; p++) acc[ii][p] = 0ull;

    // ---- o1: conv along width. staged xb/ab consumed while xn/an prefetch.
    {
        const float* xp = &Xs[i0 * XPITCH + d];
        const float* ap = &a1e[(j0 + 55) * 8 + d];
        float xb[7], ab[8];
#pragma unroll
        for (int ii = 0; ii < 7; ii++) xb[ii] = xp[ii * XPITCH];
#pragma unroll
        for (int t = 0; t < 8; t++) ab[t] = ap[t * 8];

#pragma unroll 4
        for (int jp = 0; jp < N - 1; jp++) {
            xp += 8;
            ap -= 8;
            float xn[7], an[8];
#pragma unroll
            for (int ii = 0; ii < 7; ii++) xn[ii] = xp[ii * XPITCH];
#pragma unroll
            for (int t = 0; t < 8; t++) an[t] = ap[t * 8];

            unsigned long long xd[7], apk[4];
#pragma unroll
            for (int ii = 0; ii < 7; ii++) xd[ii] = pk2(xb[ii], xb[ii]);
#pragma unroll
            for (int p = 0; p < 4; p++) apk[p] = pk2(ab[2 * p], ab[2 * p + 1]);
#pragma unroll
            for (int ii = 0; ii < 7; ii++)
#pragma unroll
                for (int p = 0; p < 4; p++) fma2(acc[ii][p], xd[ii], apk[p]);

#pragma unroll
            for (int ii = 0; ii < 7; ii++) xb[ii] = xn[ii];
#pragma unroll
            for (int t = 0; t < 8; t++) ab[t] = an[t];
        }
        // peeled last iteration
        {
            unsigned long long xd[7], apk[4];
#pragma unroll
            for (int ii = 0; ii < 7; ii++) xd[ii] = pk2(xb[ii], xb[ii]);
#pragma unroll
            for (int p = 0; p < 4; p++) apk[p] = pk2(ab[2 * p], ab[2 * p + 1]);
#pragma unroll
            for (int ii = 0; ii < 7; ii++)
#pragma unroll
                for (int p = 0; p < 4; p++) fma2(acc[ii][p], xd[ii], apk[p]);
        }
    }
    // ---- o2: conv along height. staged ab2/xb2 consumed while prefetching.
    {
        const float* xp = &Xs[j0 * 8 + d];
        const float* ap = &a2e[(i0 + 55) * 8 + d];
        float xb[8], ab[7];
#pragma unroll
        for (int t = 0; t < 8; t++) xb[t] = xp[t * 8];
#pragma unroll
        for (int ii = 0; ii < 7; ii++) ab[ii] = ap[ii * 8];

#pragma unroll 4
        for (int ip = 0; ip < N - 1; ip++) {
            xp += XPITCH;
            ap -= 8;
            float xn[8], an[7];
#pragma unroll
            for (int t = 0; t < 8; t++) xn[t] = xp[t * 8];
#pragma unroll
            for (int ii = 0; ii < 7; ii++) an[ii] = ap[ii * 8];

            unsigned long long xpk[4], ad[7];
#pragma unroll
            for (int p = 0; p < 4; p++) xpk[p] = pk2(xb[2 * p], xb[2 * p + 1]);
#pragma unroll
            for (int ii = 0; ii < 7; ii++) ad[ii] = pk2(ab[ii], ab[ii]);
#pragma unroll
            for (int ii = 0; ii < 7; ii++)
#pragma unroll
                for (int p = 0; p < 4; p++) fma2(acc[ii][p], ad[ii], xpk[p]);

#pragma unroll
            for (int t = 0; t < 8; t++) xb[t] = xn[t];
#pragma unroll
            for (int ii = 0; ii < 7; ii++) ab[ii] = an[ii];
        }
        // peeled last iteration
        {
            unsigned long long xpk[4], ad[7];
#pragma unroll
            for (int p = 0; p < 4; p++) xpk[p] = pk2(xb[2 * p], xb[2 * p + 1]);
#pragma unroll
            for (int ii = 0; ii < 7; ii++) ad[ii] = pk2(ab[ii], ab[ii]);
#pragma unroll
            for (int ii = 0; ii < 7; ii++)
#pragma unroll
                for (int p = 0; p < 4; p++) fma2(acc[ii][p], ad[ii], xpk[p]);
        }
    }

    // epilogue: t = p * (o1 + o2)
#pragma unroll
    for (int ii = 0; ii < 7; ii++) {
        int i = i0 + ii;
        long base = (long)(b * HW + i * N + j0) * D1 + dbase + d;
#pragma unroll
        for (int p = 0; p < 4; p++) {
            float lo, hi;
            unpk2(lo, hi, acc[ii][p]);
            int jj = 2 * p;
            g_t[base + (long)jj * D1] = g_p[base + (long)jj * D1] * lo;
            if (jj + 1 < 7)
                g_t[base + (long)(jj + 1) * D1] = g_p[base + (long)(jj + 1) * D1] * hi;
        }
    }
}

// ---------------- kernel D: output GEMM (TF32 mma, 2-stage pipeline, 2 blocks/SM) ----------------
#define OBPITCH 72
#define OUT_SMEM ((2 * 32 * APITCH + 2 * 32 * OBPITCH) * 4)   // 53248 B
__global__ __launch_bounds__(256, 2) void out_gemm_kernel(
    const float* __restrict__ ow, const float* __restrict__ ob,
    float* __restrict__ out) {
    extern __shared__ float smem[];
    float (*As)[32][APITCH]  = (float (*)[32][APITCH])smem;
    float (*Bs)[32][OBPITCH] = (float (*)[32][OBPITCH])(smem + 2 * 32 * APITCH);

    int tid = threadIdx.x;
    int warp = tid >> 5, lane = tid & 31;
    int wm = (warp >> 1) * 32;
    int wn = (warp & 1) * 32;
    int quad = lane >> 2, tid4 = lane & 3;
    int m0 = blockIdx.y * 128, n0 = blockIdx.x * 64;

    int lrow = tid >> 1;
    int lcb  = (tid & 1) * 16;
    int wrow = tid >> 2;
    int wkb  = (tid & 3) * 8;

    float c[2][4][4];
#pragma unroll
    for (int i = 0; i < 2; i++)
#pragma unroll
        for (int j = 0; j < 4; j++)
#pragma unroll
            for (int r = 0; r < 4; r++) c[i][j][r] = 0.0f;

    float4 pa[4];
    float4 pb2[2];

#pragma unroll
    for (int v = 0; v < 4; v++)
        pa[v] = *(const float4*)&g_t[(size_t)(m0 + lrow) * D1 + lcb + v * 4];
    pb2[0] = *(const float4*)&ow[(n0 + wrow) * D1 + wkb];
    pb2[1] = *(const float4*)&ow[(n0 + wrow) * D1 + wkb + 4];
    {
#pragma unroll
        for (int v = 0; v < 4; v++) {
            As[0][lcb + v * 4 + 0][lrow] = __uint_as_float(to_tf32(pa[v].x));
            As[0][lcb + v * 4 + 1][lrow] = __uint_as_float(to_tf32(pa[v].y));
            As[0][lcb + v * 4 + 2][lrow] = __uint_as_float(to_tf32(pa[v].z));
            As[0][lcb + v * 4 + 3][lrow] = __uint_as_float(to_tf32(pa[v].w));
        }
        Bs[0][wkb + 0][wrow] = __uint_as_float(to_tf32(pb2[0].x));
        Bs[0][wkb + 1][wrow] = __uint_as_float(to_tf32(pb2[0].y));
        Bs[0][wkb + 2][wrow] = __uint_as_float(to_tf32(pb2[0].z));
        Bs[0][wkb + 3][wrow] = __uint_as_float(to_tf32(pb2[0].w));
        Bs[0][wkb + 4][wrow] = __uint_as_float(to_tf32(pb2[1].x));
        Bs[0][wkb + 5][wrow] = __uint_as_float(to_tf32(pb2[1].y));
        Bs[0][wkb + 6][wrow] = __uint_as_float(to_tf32(pb2[1].z));
        Bs[0][wkb + 7][wrow] = __uint_as_float(to_tf32(pb2[1].w));
    }
    __syncthreads();

    int s = 0;
    for (int kb = 0; kb < D1; kb += 32, s ^= 1) {
        bool hasNext = (kb + 32) < D1;
        if (hasNext) {
            int kn = kb + 32;
#pragma unroll
            for (int v = 0; v < 4; v++)
                pa[v] = *(const float4*)&g_t[(size_t)(m0 + lrow) * D1 + kn + lcb + v * 4];
            pb2[0] = *(const float4*)&ow[(n0 + wrow) * D1 + kn + wkb];
            pb2[1] = *(const float4*)&ow[(n0 + wrow) * D1 + kn + wkb + 4];
        }

#pragma unroll
        for (int k8 = 0; k8 < 32; k8 += 8) {
            uint32_t a[2][4];
#pragma unroll
            for (int mt = 0; mt < 2; mt++) {
                int mb = wm + mt * 16;
                a[mt][0] = __float_as_uint(As[s][k8 + tid4][mb + quad]);
                a[mt][1] = __float_as_uint(As[s][k8 + tid4][mb + quad + 8]);
                a[mt][2] = __float_as_uint(As[s][k8 + tid4 + 4][mb + quad]);
                a[mt][3] = __float_as_uint(As[s][k8 + tid4 + 4][mb + quad + 8]);
            }
#pragma unroll
            for (int nt = 0; nt < 4; nt++) {
                uint32_t b[2];
                int nb = wn + nt * 8 + quad;
                b[0] = __float_as_uint(Bs[s][k8 + tid4][nb]);
                b[1] = __float_as_uint(Bs[s][k8 + tid4 + 4][nb]);
#pragma unroll
                for (int mt = 0; mt < 2; mt++)
                    mma_tf32(c[mt][nt], a[mt], b);
            }
        }

        if (hasNext) {
            int ns = s ^ 1;
#pragma unroll
            for (int v = 0; v < 4; v++) {
                As[ns][lcb + v * 4 + 0][lrow] = __uint_as_float(to_tf32(pa[v].x));
                As[ns][lcb + v * 4 + 1][lrow] = __uint_as_float(to_tf32(pa[v].y));
                As[ns][lcb + v * 4 + 2][lrow] = __uint_as_float(to_tf32(pa[v].z));
                As[ns][lcb + v * 4 + 3][lrow] = __uint_as_float(to_tf32(pa[v].w));
            }
            Bs[ns][wkb + 0][wrow] = __uint_as_float(to_tf32(pb2[0].x));
            Bs[ns][wkb + 1][wrow] = __uint_as_float(to_tf32(pb2[0].y));
            Bs[ns][wkb + 2][wrow] = __uint_as_float(to_tf32(pb2[0].z));
            Bs[ns][wkb + 3][wrow] = __uint_as_float(to_tf32(pb2[0].w));
            Bs[ns][wkb + 4][wrow] = __uint_as_float(to_tf32(pb2[1].x));
            Bs[ns][wkb + 5][wrow] = __uint_as_float(to_tf32(pb2[1].y));
            Bs[ns][wkb + 6][wrow] = __uint_as_float(to_tf32(pb2[1].z));
            Bs[ns][wkb + 7][wrow] = __uint_as_float(to_tf32(pb2[1].w));
        }
        __syncthreads();
    }

#pragma unroll
    for (int mt = 0; mt < 2; mt++) {
#pragma unroll
        for (int half = 0; half < 2; half++) {
            int m = m0 + wm + mt * 16 + quad + half * 8;
#pragma unroll
            for (int nt = 0; nt < 4; nt++) {
                int n = n0 + wn + nt * 8 + tid4 * 2;
                float2 o = make_float2(c[mt][nt][half * 2 + 0] + ob[n],
                                       c[mt][nt][half * 2 + 1] + ob[n + 1]);
                *(float2*)&out[m * EMBED + n] = o;
            }
        }
    }
}

// ---------------- launch ----------------
extern "C" void kernel_launch(void* const* d_in, const int* in_sizes, int n_in,
                              void* d_out, int out_size) {
    const float* x    = (const float*)d_in[0];
    const float* p_w  = (const float*)d_in[1];
    const float* p_b  = (const float*)d_in[2];
    const float* q_w  = (const float*)d_in[3];
    const float* q_b  = (const float*)d_in[4];
    const float* v_w  = (const float*)d_in[5];
    const float* v_b  = (const float*)d_in[6];
    const float* o_w  = (const float*)d_in[7];
    const float* o_b  = (const float*)d_in[8];
    const float* slope = (const float*)d_in[9];
    const float* t1_w0 = (const float*)d_in[10];
    const float* t1_b0 = (const float*)d_in[11];
    const float* t1_ws = (const float*)d_in[12];
    const float* t1_bs = (const float*)d_in[13];
    const float* t1_wo = (const float*)d_in[14];
    const float* t1_bo = (const float*)d_in[15];
    const float* t2_w0 = (const float*)d_in[16];
    const float* t2_b0 = (const float*)d_in[17];
    const float* t2_ws = (const float*)d_in[18];
    const float* t2_bs = (const float*)d_in[19];
    const float* t2_wo = (const float*)d_in[20];
    const float* t2_bo = (const float*)d_in[21];
    float* out = (float*)d_out;

    static const int smemC = (N * XPITCH + 2 * AELEN * 8) * (int)sizeof(float);  // 107520 B
    cudaFuncSetAttribute(toeplitz_kernel, cudaFuncAttributeMaxDynamicSharedMemorySize, smemC);
    cudaFuncSetAttribute(pqv_kernel, cudaFuncAttributeMaxDynamicSharedMemorySize, PQV_SMEM);
    cudaFuncSetAttribute(out_gemm_kernel, cudaFuncAttributeMaxDynamicSharedMemorySize, OUT_SMEM);

    rpe_hidden_kernel<<<1, 256>>>(t1_w0, t1_b0, t1_ws, t1_bs, t2_w0, t2_b0, t2_ws, t2_bs);
    rpe_out_kernel<<<2 * TWO_N, 128>>>(t1_wo, t1_bo, t2_wo, t2_bo, slope);
    pqv_kernel<<<dim3(D1 / 32, TOK / 128), 256, PQV_SMEM>>>(x, p_w, p_b, q_w, q_b, v_w, v_b);
    toeplitz_kernel<<<dim3(D1 / 8, B), 512, smemC>>>();
    out_gemm_kernel<<<dim3(EMBED / 64, TOK / 128), 256, OUT_SMEM>>>(o_w, o_b, out);
}

// round 12
// speedup vs baseline: 1.4271x; 1.4271x over previous
#include <cuda_runtime.h>
#include <cuda_bf16.h>
#include <math.h>
#include <stdint.h>

#define B 8
#define N 56
#define HW 3136           // 56*56
#define TOK 25088         // 8*56*56
#define EMBED 192
#define D1 576
#define TWO_N 112
#define RPE_H 32

// ---------------- device scratch ----------------
__device__ float g_p[TOK * D1];
__device__ float g_qv[TOK * D1];
__device__ float g_t[TOK * D1];
__device__ float g_a[2 * TWO_N * D1];   // a1 then a2
__device__ float g_h[2 * TWO_N * RPE_H];

__device__ __forceinline__ float silu_f(float x) {
    return __fdividef(x, 1.0f + __expf(-x));
}

__device__ __forceinline__ uint32_t to_tf32(float x) {
    uint32_t r;
    asm("cvt.rna.tf32.f32 %0, %1;" : "=r"(r) : "f"(x));
    return r;
}

__device__ __forceinline__ void mma_tf32(float c[4], const uint32_t a[4], const uint32_t b[2]) {
    asm volatile(
        "mma.sync.aligned.m16n8k8.row.col.f32.tf32.tf32.f32 "
        "{%0,%1,%2,%3}, {%4,%5,%6,%7}, {%8,%9}, {%0,%1,%2,%3};"
        : "+f"(c[0]), "+f"(c[1]), "+f"(c[2]), "+f"(c[3])
        : "r"(a[0]), "r"(a[1]), "r"(a[2]), "r"(a[3]), "r"(b[0]), "r"(b[1]));
}

// f32x2 packed helpers (sm_103a FFMA2 — PTX-only path)
__device__ __forceinline__ unsigned long long pk2(float lo, float hi) {
    unsigned long long r;
    asm("mov.b64 %0, {%1, %2};" : "=l"(r) : "f"(lo), "f"(hi));
    return r;
}
__device__ __forceinline__ void fma2(unsigned long long& c, unsigned long long a, unsigned long long b) {
    asm("fma.rn.f32x2 %0, %1, %2, %0;" : "+l"(c) : "l"(a), "l"(b));
}
__device__ __forceinline__ void unpk2(float& lo, float& hi, unsigned long long v) {
    asm("mov.b64 {%0, %1}, %2;" : "=f"(lo), "=f"(hi) : "l"(v));
}

// ---------------- kernel A1: RPE hidden layers ----------------
__global__ void rpe_hidden_kernel(const float* __restrict__ w0a, const float* __restrict__ b0a,
                                  const float* __restrict__ wsa, const float* __restrict__ bsa,
                                  const float* __restrict__ w0b, const float* __restrict__ b0b,
                                  const float* __restrict__ wsb, const float* __restrict__ bsb) {
    int t = threadIdx.x;
    int tno = t >> 7;
    int row = t & 127;
    if (row >= TWO_N) return;
    const float* W0 = tno ? w0b : w0a;
    const float* B0 = tno ? b0b : b0a;
    const float* WS = tno ? wsb : wsa;
    const float* BS = tno ? bsb : bsa;

    float tv;
    if (row == 0 || row == 56) tv = 0.0f;
    else if (row < 56) tv = (float)row;
    else tv = -(float)(row - 56);

    float h[RPE_H];
#pragma unroll
    for (int j = 0; j < RPE_H; j++) h[j] = tv * W0[j] + B0[j];

    for (int L = 0; L < 3; L++) {
        float hn[RPE_H];
#pragma unroll
        for (int j = 0; j < RPE_H; j++) {
            float s = BS[L * RPE_H + j];
#pragma unroll
            for (int k = 0; k < RPE_H; k++)
                s += fmaxf(h[k], 0.0f) * WS[L * RPE_H * RPE_H + j * RPE_H + k];
            hn[j] = s;
        }
#pragma unroll
        for (int j = 0; j < RPE_H; j++) h[j] = hn[j];
    }
#pragma unroll
    for (int k = 0; k < RPE_H; k++)
        g_h[(tno * TWO_N + row) * RPE_H + k] = fmaxf(h[k], 0.0f);
}

// ---------------- kernel A2: RPE output layer * decay ----------------
__global__ void rpe_out_kernel(const float* __restrict__ wo1, const float* __restrict__ bo1,
                               const float* __restrict__ wo2, const float* __restrict__ bo2,
                               const float* __restrict__ slope) {
    int bx = blockIdx.x;
    int tno = bx / TWO_N;
    int row = bx % TWO_N;
    const float* WO = tno ? wo2 : wo1;
    const float* BO = tno ? bo2 : bo1;

    __shared__ float hs[RPE_H];
    if (threadIdx.x < RPE_H)
        hs[threadIdx.x] = g_h[(tno * TWO_N + row) * RPE_H + threadIdx.x];
    __syncthreads();

    int e;
    if (row == 0 || row == 56) e = 0;
    else if (row < 56) e = row;
    else e = TWO_N - row;

    for (int d = threadIdx.x; d < D1; d += blockDim.x) {
        float s = BO[d];
#pragma unroll
        for (int k = 0; k < RPE_H; k++) s += hs[k] * WO[d * RPE_H + k];
        float sl = slope[d];
        sl = fminf(fmaxf(sl, 0.0f), 1.0f);
        sl = 0.95f + 0.05f * sl;
        float dec = (e == 0) ? 1.0f : __powf(sl, (float)e);
        g_a[(tno * TWO_N + row) * D1 + d] = s * dec;
    }
}

// ---------------- kernel B: fused p / q*v GEMMs (TF32 mma, 2-stage pipeline, BN=32) ----------------
#define APITCH 136   // ≡ 8 mod 32 -> conflict-free frag loads
#define BPITCH 40    // ≡ 8 mod 32
#define PQV_SMEM ((2 * 32 * APITCH + 2 * 3 * 32 * BPITCH) * 4)   // 65536 B

__global__ __launch_bounds__(256, 2) void pqv_kernel(
    const float* __restrict__ x,
    const float* __restrict__ pw, const float* __restrict__ pb,
    const float* __restrict__ qw, const float* __restrict__ qb,
    const float* __restrict__ vw, const float* __restrict__ vb) {
    extern __shared__ float smem[];
    float (*As)[32][APITCH]    = (float (*)[32][APITCH])smem;
    float (*Bs)[3][32][BPITCH] = (float (*)[3][32][BPITCH])(smem + 2 * 32 * APITCH);

    int tid = threadIdx.x;
    int warp = tid >> 5, lane = tid & 31;
    int wm = (warp >> 1) * 32;
    int wn = (warp & 1) * 16;
    int quad = lane >> 2, tid4 = lane & 3;
    int m0 = blockIdx.y * 128, n0 = blockIdx.x * 32;

    int lrow = tid >> 1;
    int lcb  = (tid & 1) * 16;
    int wrow = tid >> 3;
    int wkb  = (tid & 7) * 4;

    const float* wmats[3] = {pw, qw, vw};

    float c[3][2][2][4];
#pragma unroll
    for (int mt2 = 0; mt2 < 3; mt2++)
#pragma unroll
        for (int i = 0; i < 2; i++)
#pragma unroll
            for (int j = 0; j < 2; j++)
#pragma unroll
                for (int r = 0; r < 4; r++) c[mt2][i][j][r] = 0.0f;

    float4 pa[4];
    float4 pwv[3];

#pragma unroll
    for (int v = 0; v < 4; v++)
        pa[v] = *(const float4*)&x[(m0 + lrow) * EMBED + lcb + v * 4];
#pragma unroll
    for (int mat = 0; mat < 3; mat++)
        pwv[mat] = *(const float4*)&wmats[mat][(n0 + wrow) * EMBED + wkb];
    {
#pragma unroll
        for (int v = 0; v < 4; v++) {
            As[0][lcb + v * 4 + 0][lrow] = __uint_as_float(to_tf32(pa[v].x));
            As[0][lcb + v * 4 + 1][lrow] = __uint_as_float(to_tf32(pa[v].y));
            As[0][lcb + v * 4 + 2][lrow] = __uint_as_float(to_tf32(pa[v].z));
            As[0][lcb + v * 4 + 3][lrow] = __uint_as_float(to_tf32(pa[v].w));
        }
#pragma unroll
        for (int mat = 0; mat < 3; mat++) {
            Bs[0][mat][wkb + 0][wrow] = __uint_as_float(to_tf32(pwv[mat].x));
            Bs[0][mat][wkb + 1][wrow] = __uint_as_float(to_tf32(pwv[mat].y));
            Bs[0][mat][wkb + 2][wrow] = __uint_as_float(to_tf32(pwv[mat].z));
            Bs[0][mat][wkb + 3][wrow] = __uint_as_float(to_tf32(pwv[mat].w));
        }
    }
    __syncthreads();

    int s = 0;
    for (int kb = 0; kb < EMBED; kb += 32, s ^= 1) {
        bool hasNext = (kb + 32) < EMBED;
        if (hasNext) {
            int kn = kb + 32;
#pragma unroll
            for (int v = 0; v < 4; v++)
                pa[v] = *(const float4*)&x[(m0 + lrow) * EMBED + kn + lcb + v * 4];
#pragma unroll
            for (int mat = 0; mat < 3; mat++)
                pwv[mat] = *(const float4*)&wmats[mat][(n0 + wrow) * EMBED + kn + wkb];
        }

#pragma unroll
        for (int k8 = 0; k8 < 32; k8 += 8) {
            uint32_t a[2][4];
#pragma unroll
            for (int mt = 0; mt < 2; mt++) {
                int mb = wm + mt * 16;
                a[mt][0] = __float_as_uint(As[s][k8 + tid4][mb + quad]);
                a[mt][1] = __float_as_uint(As[s][k8 + tid4][mb + quad + 8]);
                a[mt][2] = __float_as_uint(As[s][k8 + tid4 + 4][mb + quad]);
                a[mt][3] = __float_as_uint(As[s][k8 + tid4 + 4][mb + quad + 8]);
            }
#pragma unroll
            for (int mat = 0; mat < 3; mat++) {
#pragma unroll
                for (int nt = 0; nt < 2; nt++) {
                    uint32_t b[2];
                    int nb = wn + nt * 8 + quad;
                    b[0] = __float_as_uint(Bs[s][mat][k8 + tid4][nb]);
                    b[1] = __float_as_uint(Bs[s][mat][k8 + tid4 + 4][nb]);
#pragma unroll
                    for (int mt = 0; mt < 2; mt++)
                        mma_tf32(c[mat][mt][nt], a[mt], b);
                }
            }
        }

        if (hasNext) {
            int ns = s ^ 1;
#pragma unroll
            for (int v = 0; v < 4; v++) {
                As[ns][lcb + v * 4 + 0][lrow] = __uint_as_float(to_tf32(pa[v].x));
                As[ns][lcb + v * 4 + 1][lrow] = __uint_as_float(to_tf32(pa[v].y));
                As[ns][lcb + v * 4 + 2][lrow] = __uint_as_float(to_tf32(pa[v].z));
                As[ns][lcb + v * 4 + 3][lrow] = __uint_as_float(to_tf32(pa[v].w));
            }
#pragma unroll
            for (int mat = 0; mat < 3; mat++) {
                Bs[ns][mat][wkb + 0][wrow] = __uint_as_float(to_tf32(pwv[mat].x));
                Bs[ns][mat][wkb + 1][wrow] = __uint_as_float(to_tf32(pwv[mat].y));
                Bs[ns][mat][wkb + 2][wrow] = __uint_as_float(to_tf32(pwv[mat].z));
                Bs[ns][mat][wkb + 3][wrow] = __uint_as_float(to_tf32(pwv[mat].w));
            }
        }
        __syncthreads();
    }

#pragma unroll
    for (int mt = 0; mt < 2; mt++) {
#pragma unroll
        for (int half = 0; half < 2; half++) {
            int m = m0 + wm + mt * 16 + quad + half * 8;
#pragma unroll
            for (int nt = 0; nt < 2; nt++) {
                int n = n0 + wn + nt * 8 + tid4 * 2;
                float cp0 = c[0][mt][nt][half * 2 + 0] + pb[n];
                float cp1 = c[0][mt][nt][half * 2 + 1] + pb[n + 1];
                float cq0 = c[1][mt][nt][half * 2 + 0] + qb[n];
                float cq1 = c[1][mt][nt][half * 2 + 1] + qb[n + 1];
                float cv0 = c[2][mt][nt][half * 2 + 0] + vb[n];
                float cv1 = c[2][mt][nt][half * 2 + 1] + vb[n + 1];
                float2 pv = make_float2(silu_f(cp0), silu_f(cp1));
                float2 qv = make_float2(silu_f(cq0) * silu_f(cv0),
                                        silu_f(cq1) * silu_f(cv1));
                *(float2*)&g_p[m * D1 + n] = pv;
                *(float2*)&g_qv[m * D1 + n] = qv;
            }
        }
    }
}

// ---------------- kernel C: axial Toeplitz + gate (f32x2 packed, proven R4 body) ----------------
// One block per (batch, 8-channel group). 512 threads: tid = (ti*8+tj)*8 + d.
#define XPITCH 448
#define AELEN 112
__global__ __launch_bounds__(512) void toeplitz_kernel() {
    extern __shared__ float sm[];
    float* Xs  = sm;
    float* a1e = sm + N * XPITCH;
    float* a2e = a1e + AELEN * 8;

    int dg = blockIdx.x;
    int b  = blockIdx.y;
    int dbase = dg * 8;
    int tid = threadIdx.x;

    for (int idx = tid; idx < HW * 2; idx += 512) {
        int pos = idx >> 1;
        int q = (idx & 1) * 4;
        float4 v = *(const float4*)&g_qv[(size_t)(b * HW + pos) * D1 + dbase + q];
        int i = pos / N, j = pos % N;
        *(float4*)&Xs[i * XPITCH + j * 8 + q] = v;
    }
    for (int idx = tid; idx < AELEN * 8; idx += 512) {
        int k = idx >> 3, dd = idx & 7;
        int src = (k + 57) % TWO_N;
        a1e[idx] = g_a[src * D1 + dbase + dd];
        a2e[idx] = g_a[TWO_N * D1 + src * D1 + dbase + dd];
    }
    __syncthreads();

    int d  = tid & 7;
    int tp = tid >> 3;
    int tj = tp & 7;
    int ti = tp >> 3;
    int i0 = ti * 7, j0 = tj * 7;

    unsigned long long acc[7][4];
#pragma unroll
    for (int ii = 0; ii < 7; ii++)
#pragma unroll
        for (int p = 0; p < 4; p++) acc[ii][p] = 0ull;

    {
        const float* xp = &Xs[i0 * XPITCH + d];
        const float* ap = &a1e[(j0 + 55) * 8 + d];
#pragma unroll 4
        for (int jp = 0; jp < N; jp++) {
            unsigned long long xd[7];
#pragma unroll
            for (int ii = 0; ii < 7; ii++) {
                float xv = xp[ii * XPITCH];
                xd[ii] = pk2(xv, xv);
            }
            float av[8];
#pragma unroll
            for (int t = 0; t < 8; t++) av[t] = ap[t * 8];
            unsigned long long apk[4];
#pragma unroll
            for (int p = 0; p < 4; p++) apk[p] = pk2(av[2 * p], av[2 * p + 1]);
#pragma unroll
            for (int ii = 0; ii < 7; ii++)
#pragma unroll
                for (int p = 0; p < 4; p++) fma2(acc[ii][p], xd[ii], apk[p]);
            xp += 8;
            ap -= 8;
        }
    }
    {
        const float* xp = &Xs[j0 * 8 + d];
        const float* ap = &a2e[(i0 + 55) * 8 + d];
#pragma unroll 4
        for (int ip = 0; ip < N; ip++) {
            float xv[8];
#pragma unroll
            for (int t = 0; t < 8; t++) xv[t] = xp[t * 8];
            unsigned long long xpk[4];
#pragma unroll
            for (int p = 0; p < 4; p++) xpk[p] = pk2(xv[2 * p], xv[2 * p + 1]);
            unsigned long long ad[7];
#pragma unroll
            for (int ii = 0; ii < 7; ii++) {
                float a = ap[ii * 8];
                ad[ii] = pk2(a, a);
            }
#pragma unroll
            for (int ii = 0; ii < 7; ii++)
#pragma unroll
                for (int p = 0; p < 4; p++) fma2(acc[ii][p], ad[ii], xpk[p]);
            xp += XPITCH;
            ap -= 8;
        }
    }

#pragma unroll
    for (int ii = 0; ii < 7; ii++) {
        int i = i0 + ii;
        long base = (long)(b * HW + i * N + j0) * D1 + dbase + d;
#pragma unroll
        for (int p = 0; p < 4; p++) {
            float lo, hi;
            unpk2(lo, hi, acc[ii][p]);
            int jj = 2 * p;
            g_t[base + (long)jj * D1] = g_p[base + (long)jj * D1] * lo;
            if (jj + 1 < 7)
                g_t[base + (long)(jj + 1) * D1] = g_p[base + (long)(jj + 1) * D1] * hi;
        }
    }
}

// ---------------- kernel D: output GEMM (TF32 mma, 2-stage pipeline, 2 blocks/SM) ----------------
#define OBPITCH 72
#define OUT_SMEM ((2 * 32 * APITCH + 2 * 32 * OBPITCH) * 4)   // 53248 B
__global__ __launch_bounds__(256, 2) void out_gemm_kernel(
    const float* __restrict__ ow, const float* __restrict__ ob,
    float* __restrict__ out) {
    extern __shared__ float smem[];
    float (*As)[32][APITCH]  = (float (*)[32][APITCH])smem;
    float (*Bs)[32][OBPITCH] = (float (*)[32][OBPITCH])(smem + 2 * 32 * APITCH);

    int tid = threadIdx.x;
    int warp = tid >> 5, lane = tid & 31;
    int wm = (warp >> 1) * 32;
    int wn = (warp & 1) * 32;
    int quad = lane >> 2, tid4 = lane & 3;
    int m0 = blockIdx.y * 128, n0 = blockIdx.x * 64;

    int lrow = tid >> 1;
    int lcb  = (tid & 1) * 16;
    int wrow = tid >> 2;
    int wkb  = (tid & 3) * 8;

    float c[2][4][4];
#pragma unroll
    for (int i = 0; i < 2; i++)
#pragma unroll
        for (int j = 0; j < 4; j++)
#pragma unroll
            for (int r = 0; r < 4; r++) c[i][j][r] = 0.0f;

    float4 pa[4];
    float4 pb2[2];

#pragma unroll
    for (int v = 0; v < 4; v++)
        pa[v] = *(const float4*)&g_t[(size_t)(m0 + lrow) * D1 + lcb + v * 4];
    pb2[0] = *(const float4*)&ow[(n0 + wrow) * D1 + wkb];
    pb2[1] = *(const float4*)&ow[(n0 + wrow) * D1 + wkb + 4];
    {
#pragma unroll
        for (int v = 0; v < 4; v++) {
            As[0][lcb + v * 4 + 0][lrow] = __uint_as_float(to_tf32(pa[v].x));
            As[0][lcb + v * 4 + 1][lrow] = __uint_as_float(to_tf32(pa[v].y));
            As[0][lcb + v * 4 + 2][lrow] = __uint_as_float(to_tf32(pa[v].z));
            As[0][lcb + v * 4 + 3][lrow] = __uint_as_float(to_tf32(pa[v].w));
        }
        Bs[0][wkb + 0][wrow] = __uint_as_float(to_tf32(pb2[0].x));
        Bs[0][wkb + 1][wrow] = __uint_as_float(to_tf32(pb2[0].y));
        Bs[0][wkb + 2][wrow] = __uint_as_float(to_tf32(pb2[0].z));
        Bs[0][wkb + 3][wrow] = __uint_as_float(to_tf32(pb2[0].w));
        Bs[0][wkb + 4][wrow] = __uint_as_float(to_tf32(pb2[1].x));
        Bs[0][wkb + 5][wrow] = __uint_as_float(to_tf32(pb2[1].y));
        Bs[0][wkb + 6][wrow] = __uint_as_float(to_tf32(pb2[1].z));
        Bs[0][wkb + 7][wrow] = __uint_as_float(to_tf32(pb2[1].w));
    }
    __syncthreads();

    int s = 0;
    for (int kb = 0; kb < D1; kb += 32, s ^= 1) {
        bool hasNext = (kb + 32) < D1;
        if (hasNext) {
            int kn = kb + 32;
#pragma unroll
            for (int v = 0; v < 4; v++)
                pa[v] = *(const float4*)&g_t[(size_t)(m0 + lrow) * D1 + kn + lcb + v * 4];
            pb2[0] = *(const float4*)&ow[(n0 + wrow) * D1 + kn + wkb];
            pb2[1] = *(const float4*)&ow[(n0 + wrow) * D1 + kn + wkb + 4];
        }

#pragma unroll
        for (int k8 = 0; k8 < 32; k8 += 8) {
            uint32_t a[2][4];
#pragma unroll
            for (int mt = 0; mt < 2; mt++) {
                int mb = wm + mt * 16;
                a[mt][0] = __float_as_uint(As[s][k8 + tid4][mb + quad]);
                a[mt][1] = __float_as_uint(As[s][k8 + tid4][mb + quad + 8]);
                a[mt][2] = __float_as_uint(As[s][k8 + tid4 + 4][mb + quad]);
                a[mt][3] = __float_as_uint(As[s][k8 + tid4 + 4][mb + quad + 8]);
            }
#pragma unroll
            for (int nt = 0; nt < 4; nt++) {
                uint32_t b[2];
                int nb = wn + nt * 8 + quad;
                b[0] = __float_as_uint(Bs[s][k8 + tid4][nb]);
                b[1] = __float_as_uint(Bs[s][k8 + tid4 + 4][nb]);
#pragma unroll
                for (int mt = 0; mt < 2; mt++)
                    mma_tf32(c[mt][nt], a[mt], b);
            }
        }

        if (hasNext) {
            int ns = s ^ 1;
#pragma unroll
            for (int v = 0; v < 4; v++) {
                As[ns][lcb + v * 4 + 0][lrow] = __uint_as_float(to_tf32(pa[v].x));
                As[ns][lcb + v * 4 + 1][lrow] = __uint_as_float(to_tf32(pa[v].y));
                As[ns][lcb + v * 4 + 2][lrow] = __uint_as_float(to_tf32(pa[v].z));
                As[ns][lcb + v * 4 + 3][lrow] = __uint_as_float(to_tf32(pa[v].w));
            }
            Bs[ns][wkb + 0][wrow] = __uint_as_float(to_tf32(pb2[0].x));
            Bs[ns][wkb + 1][wrow] = __uint_as_float(to_tf32(pb2[0].y));
            Bs[ns][wkb + 2][wrow] = __uint_as_float(to_tf32(pb2[0].z));
            Bs[ns][wkb + 3][wrow] = __uint_as_float(to_tf32(pb2[0].w));
            Bs[ns][wkb + 4][wrow] = __uint_as_float(to_tf32(pb2[1].x));
            Bs[ns][wkb + 5][wrow] = __uint_as_float(to_tf32(pb2[1].y));
            Bs[ns][wkb + 6][wrow] = __uint_as_float(to_tf32(pb2[1].z));
            Bs[ns][wkb + 7][wrow] = __uint_as_float(to_tf32(pb2[1].w));
        }
        __syncthreads();
    }

#pragma unroll
    for (int mt = 0; mt < 2; mt++) {
#pragma unroll
        for (int half = 0; half < 2; half++) {
            int m = m0 + wm + mt * 16 + quad + half * 8;
#pragma unroll
            for (int nt = 0; nt < 4; nt++) {
                int n = n0 + wn + nt * 8 + tid4 * 2;
                float2 o = make_float2(c[mt][nt][half * 2 + 0] + ob[n],
                                       c[mt][nt][half * 2 + 1] + ob[n + 1]);
                *(float2*)&out[m * EMBED + n] = o;
            }
        }
    }
}

// ---------------- launch ----------------
extern "C" void kernel_launch(void* const* d_in, const int* in_sizes, int n_in,
                              void* d_out, int out_size) {
    const float* x    = (const float*)d_in[0];
    const float* p_w  = (const float*)d_in[1];
    const float* p_b  = (const float*)d_in[2];
    const float* q_w  = (const float*)d_in[3];
    const float* q_b  = (const float*)d_in[4];
    const float* v_w  = (const float*)d_in[5];
    const float* v_b  = (const float*)d_in[6];
    const float* o_w  = (const float*)d_in[7];
    const float* o_b  = (const float*)d_in[8];
    const float* slope = (const float*)d_in[9];
    const float* t1_w0 = (const float*)d_in[10];
    const float* t1_b0 = (const float*)d_in[11];
    const float* t1_ws = (const float*)d_in[12];
    const float* t1_bs = (const float*)d_in[13];
    const float* t1_wo = (const float*)d_in[14];
    const float* t1_bo = (const float*)d_in[15];
    const float* t2_w0 = (const float*)d_in[16];
    const float* t2_b0 = (const float*)d_in[17];
    const float* t2_ws = (const float*)d_in[18];
    const float* t2_bs = (const float*)d_in[19];
    const float* t2_wo = (const float*)d_in[20];
    const float* t2_bo = (const float*)d_in[21];
    float* out = (float*)d_out;

    static const int smemC = (N * XPITCH + 2 * AELEN * 8) * (int)sizeof(float);  // 107520 B
    cudaFuncSetAttribute(toeplitz_kernel, cudaFuncAttributeMaxDynamicSharedMemorySize, smemC);
    cudaFuncSetAttribute(pqv_kernel, cudaFuncAttributeMaxDynamicSharedMemorySize, PQV_SMEM);
    cudaFuncSetAttribute(out_gemm_kernel, cudaFuncAttributeMaxDynamicSharedMemorySize, OUT_SMEM);

    rpe_hidden_kernel<<<1, 256>>>(t1_w0, t1_b0, t1_ws, t1_bs, t2_w0, t2_b0, t2_ws, t2_bs);
    rpe_out_kernel<<<2 * TWO_N, 128>>>(t1_wo, t1_bo, t2_wo, t2_bo, slope);
    pqv_kernel<<<dim3(D1 / 32, TOK / 128), 256, PQV_SMEM>>>(x, p_w, p_b, q_w, q_b, v_w, v_b);
    toeplitz_kernel<<<dim3(D1 / 8, B), 512, smemC>>>();
    out_gemm_kernel<<<dim3(EMBED / 64, TOK / 128), 256, OUT_SMEM>>>(o_w, o_b, out);
}

// round 13
// speedup vs baseline: 1.6616x; 1.1644x over previous
#include <cuda_runtime.h>
#include <cuda_bf16.h>
#include <math.h>
#include <stdint.h>

#define B 8
#define N 56
#define HW 3136           // 56*56
#define TOK 25088         // 8*56*56
#define EMBED 192
#define D1 576
#define TWO_N 112
#define RPE_H 32

// ---------------- device scratch ----------------
__device__ float g_p[TOK * D1];
__device__ float g_qv[TOK * D1];
__device__ float g_t[TOK * D1];
__device__ float g_a[2 * TWO_N * D1];   // a1 then a2
__device__ float g_h[2 * TWO_N * RPE_H];

__device__ __forceinline__ float silu_f(float x) {
    return __fdividef(x, 1.0f + __expf(-x));
}

__device__ __forceinline__ uint32_t to_tf32(float x) {
    uint32_t r;
    asm("cvt.rna.tf32.f32 %0, %1;" : "=r"(r) : "f"(x));
    return r;
}

__device__ __forceinline__ void mma_tf32(float c[4], const uint32_t a[4], const uint32_t b[2]) {
    asm volatile(
        "mma.sync.aligned.m16n8k8.row.col.f32.tf32.tf32.f32 "
        "{%0,%1,%2,%3}, {%4,%5,%6,%7}, {%8,%9}, {%0,%1,%2,%3};"
        : "+f"(c[0]), "+f"(c[1]), "+f"(c[2]), "+f"(c[3])
        : "r"(a[0]), "r"(a[1]), "r"(a[2]), "r"(a[3]), "r"(b[0]), "r"(b[1]));
}

// ---------------- kernel A1: RPE hidden layers ----------------
__global__ void rpe_hidden_kernel(const float* __restrict__ w0a, const float* __restrict__ b0a,
                                  const float* __restrict__ wsa, const float* __restrict__ bsa,
                                  const float* __restrict__ w0b, const float* __restrict__ b0b,
                                  const float* __restrict__ wsb, const float* __restrict__ bsb) {
    int t = threadIdx.x;
    int tno = t >> 7;
    int row = t & 127;
    if (row >= TWO_N) return;
    const float* W0 = tno ? w0b : w0a;
    const float* B0 = tno ? b0b : b0a;
    const float* WS = tno ? wsb : wsa;
    const float* BS = tno ? bsb : bsa;

    float tv;
    if (row == 0 || row == 56) tv = 0.0f;
    else if (row < 56) tv = (float)row;
    else tv = -(float)(row - 56);

    float h[RPE_H];
#pragma unroll
    for (int j = 0; j < RPE_H; j++) h[j] = tv * W0[j] + B0[j];

    for (int L = 0; L < 3; L++) {
        float hn[RPE_H];
#pragma unroll
        for (int j = 0; j < RPE_H; j++) {
            float s = BS[L * RPE_H + j];
#pragma unroll
            for (int k = 0; k < RPE_H; k++)
                s += fmaxf(h[k], 0.0f) * WS[L * RPE_H * RPE_H + j * RPE_H + k];
            hn[j] = s;
        }
#pragma unroll
        for (int j = 0; j < RPE_H; j++) h[j] = hn[j];
    }
#pragma unroll
    for (int k = 0; k < RPE_H; k++)
        g_h[(tno * TWO_N + row) * RPE_H + k] = fmaxf(h[k], 0.0f);
}

// ---------------- kernel A2: RPE output layer * decay ----------------
__global__ void rpe_out_kernel(const float* __restrict__ wo1, const float* __restrict__ bo1,
                               const float* __restrict__ wo2, const float* __restrict__ bo2,
                               const float* __restrict__ slope) {
    int bx = blockIdx.x;
    int tno = bx / TWO_N;
    int row = bx % TWO_N;
    const float* WO = tno ? wo2 : wo1;
    const float* BO = tno ? bo2 : bo1;

    __shared__ float hs[RPE_H];
    if (threadIdx.x < RPE_H)
        hs[threadIdx.x] = g_h[(tno * TWO_N + row) * RPE_H + threadIdx.x];
    __syncthreads();

    int e;
    if (row == 0 || row == 56) e = 0;
    else if (row < 56) e = row;
    else e = TWO_N - row;

    for (int d = threadIdx.x; d < D1; d += blockDim.x) {
        float s = BO[d];
#pragma unroll
        for (int k = 0; k < RPE_H; k++) s += hs[k] * WO[d * RPE_H + k];
        float sl = slope[d];
        sl = fminf(fmaxf(sl, 0.0f), 1.0f);
        sl = 0.95f + 0.05f * sl;
        float dec = (e == 0) ? 1.0f : __powf(sl, (float)e);
        g_a[(tno * TWO_N + row) * D1 + d] = s * dec;
    }
}

// ---------------- kernel B: fused p / q*v GEMMs (TF32 mma, 2-stage pipeline, BN=32) ----------------
#define APITCH 136   // ≡ 8 mod 32 -> conflict-free frag loads
#define BPITCH 40    // ≡ 8 mod 32
#define PQV_SMEM ((2 * 32 * APITCH + 2 * 3 * 32 * BPITCH) * 4)   // 65536 B

__global__ __launch_bounds__(256, 2) void pqv_kernel(
    const float* __restrict__ x,
    const float* __restrict__ pw, const float* __restrict__ pb,
    const float* __restrict__ qw, const float* __restrict__ qb,
    const float* __restrict__ vw, const float* __restrict__ vb) {
    extern __shared__ float smem[];
    float (*As)[32][APITCH]    = (float (*)[32][APITCH])smem;
    float (*Bs)[3][32][BPITCH] = (float (*)[3][32][BPITCH])(smem + 2 * 32 * APITCH);

    int tid = threadIdx.x;
    int warp = tid >> 5, lane = tid & 31;
    int wm = (warp >> 1) * 32;
    int wn = (warp & 1) * 16;
    int quad = lane >> 2, tid4 = lane & 3;
    int m0 = blockIdx.y * 128, n0 = blockIdx.x * 32;

    int lrow = tid >> 1;
    int lcb  = (tid & 1) * 16;
    int wrow = tid >> 3;
    int wkb  = (tid & 7) * 4;

    const float* wmats[3] = {pw, qw, vw};

    float c[3][2][2][4];
#pragma unroll
    for (int mt2 = 0; mt2 < 3; mt2++)
#pragma unroll
        for (int i = 0; i < 2; i++)
#pragma unroll
            for (int j = 0; j < 2; j++)
#pragma unroll
                for (int r = 0; r < 4; r++) c[mt2][i][j][r] = 0.0f;

    float4 pa[4];
    float4 pwv[3];

#pragma unroll
    for (int v = 0; v < 4; v++)
        pa[v] = *(const float4*)&x[(m0 + lrow) * EMBED + lcb + v * 4];
#pragma unroll
    for (int mat = 0; mat < 3; mat++)
        pwv[mat] = *(const float4*)&wmats[mat][(n0 + wrow) * EMBED + wkb];
    {
#pragma unroll
        for (int v = 0; v < 4; v++) {
            As[0][lcb + v * 4 + 0][lrow] = __uint_as_float(to_tf32(pa[v].x));
            As[0][lcb + v * 4 + 1][lrow] = __uint_as_float(to_tf32(pa[v].y));
            As[0][lcb + v * 4 + 2][lrow] = __uint_as_float(to_tf32(pa[v].z));
            As[0][lcb + v * 4 + 3][lrow] = __uint_as_float(to_tf32(pa[v].w));
        }
#pragma unroll
        for (int mat = 0; mat < 3; mat++) {
            Bs[0][mat][wkb + 0][wrow] = __uint_as_float(to_tf32(pwv[mat].x));
            Bs[0][mat][wkb + 1][wrow] = __uint_as_float(to_tf32(pwv[mat].y));
            Bs[0][mat][wkb + 2][wrow] = __uint_as_float(to_tf32(pwv[mat].z));
            Bs[0][mat][wkb + 3][wrow] = __uint_as_float(to_tf32(pwv[mat].w));
        }
    }
    __syncthreads();

    int s = 0;
    for (int kb = 0; kb < EMBED; kb += 32, s ^= 1) {
        bool hasNext = (kb + 32) < EMBED;
        if (hasNext) {
            int kn = kb + 32;
#pragma unroll
            for (int v = 0; v < 4; v++)
                pa[v] = *(const float4*)&x[(m0 + lrow) * EMBED + kn + lcb + v * 4];
#pragma unroll
            for (int mat = 0; mat < 3; mat++)
                pwv[mat] = *(const float4*)&wmats[mat][(n0 + wrow) * EMBED + kn + wkb];
        }

#pragma unroll
        for (int k8 = 0; k8 < 32; k8 += 8) {
            uint32_t a[2][4];
#pragma unroll
            for (int mt = 0; mt < 2; mt++) {
                int mb = wm + mt * 16;
                a[mt][0] = __float_as_uint(As[s][k8 + tid4][mb + quad]);
                a[mt][1] = __float_as_uint(As[s][k8 + tid4][mb + quad + 8]);
                a[mt][2] = __float_as_uint(As[s][k8 + tid4 + 4][mb + quad]);
                a[mt][3] = __float_as_uint(As[s][k8 + tid4 + 4][mb + quad + 8]);
            }
#pragma unroll
            for (int mat = 0; mat < 3; mat++) {
#pragma unroll
                for (int nt = 0; nt < 2; nt++) {
                    uint32_t b[2];
                    int nb = wn + nt * 8 + quad;
                    b[0] = __float_as_uint(Bs[s][mat][k8 + tid4][nb]);
                    b[1] = __float_as_uint(Bs[s][mat][k8 + tid4 + 4][nb]);
#pragma unroll
                    for (int mt = 0; mt < 2; mt++)
                        mma_tf32(c[mat][mt][nt], a[mt], b);
                }
            }
        }

        if (hasNext) {
            int ns = s ^ 1;
#pragma unroll
            for (int v = 0; v < 4; v++) {
                As[ns][lcb + v * 4 + 0][lrow] = __uint_as_float(to_tf32(pa[v].x));
                As[ns][lcb + v * 4 + 1][lrow] = __uint_as_float(to_tf32(pa[v].y));
                As[ns][lcb + v * 4 + 2][lrow] = __uint_as_float(to_tf32(pa[v].z));
                As[ns][lcb + v * 4 + 3][lrow] = __uint_as_float(to_tf32(pa[v].w));
            }
#pragma unroll
            for (int mat = 0; mat < 3; mat++) {
                Bs[ns][mat][wkb + 0][wrow] = __uint_as_float(to_tf32(pwv[mat].x));
                Bs[ns][mat][wkb + 1][wrow] = __uint_as_float(to_tf32(pwv[mat].y));
                Bs[ns][mat][wkb + 2][wrow] = __uint_as_float(to_tf32(pwv[mat].z));
                Bs[ns][mat][wkb + 3][wrow] = __uint_as_float(to_tf32(pwv[mat].w));
            }
        }
        __syncthreads();
    }

#pragma unroll
    for (int mt = 0; mt < 2; mt++) {
#pragma unroll
        for (int half = 0; half < 2; half++) {
            int m = m0 + wm + mt * 16 + quad + half * 8;
#pragma unroll
            for (int nt = 0; nt < 2; nt++) {
                int n = n0 + wn + nt * 8 + tid4 * 2;
                float cp0 = c[0][mt][nt][half * 2 + 0] + pb[n];
                float cp1 = c[0][mt][nt][half * 2 + 1] + pb[n + 1];
                float cq0 = c[1][mt][nt][half * 2 + 0] + qb[n];
                float cq1 = c[1][mt][nt][half * 2 + 1] + qb[n + 1];
                float cv0 = c[2][mt][nt][half * 2 + 0] + vb[n];
                float cv1 = c[2][mt][nt][half * 2 + 1] + vb[n + 1];
                float2 pv = make_float2(silu_f(cp0), silu_f(cp1));
                float2 qv = make_float2(silu_f(cq0) * silu_f(cv0),
                                        silu_f(cq1) * silu_f(cv1));
                *(float2*)&g_p[m * D1 + n] = pv;
                *(float2*)&g_qv[m * D1 + n] = qv;
            }
        }
    }
}

// ---------------- kernel C: axial Toeplitz + gate (single-pass TF32 tensor-core) ----------------
// Block = (b, 8-channel group), 512 threads = 16 warps.
// Warp w: channel d = w&7, axis = w>>3 (0: o1 = X·A1 along width, 1: o2 = A2·X along height).
// Per-channel 64x64 (padded) smem plane, pitch 72 floats. Coeff vectors a1p/a2p[d][128]
// hold a[(idx-63) mod 112] so A_mat[k][n] = a[(n-k) mod 112] = ap[n-k+63].
// Layout/indexing identical to the R5-verified kernel; single tf32 pass (no hi/lo split).
#define XPL   4608    // plane: 64 rows * 72
#define XPIT  72
#define RPL   1940    // res plane: 32 rows * 60 (+20 pad)
#define RPIT  60
#define XOFF  0
#define A1OFF (8 * XPL)            // 36864
#define A2OFF (A1OFF + 8 * 128)    // 37888
#define RESOFF (A2OFF + 8 * 128)   // 38912
#define SMEMC_FLOATS (RESOFF + 8 * RPL)   // 54432 floats = 217728 B

__global__ __launch_bounds__(512, 1) void toeplitz_kernel() {
    extern __shared__ float sm[];

    int dg = blockIdx.x;                    // 0..71
    int b  = blockIdx.y;                    // 0..7
    int dbase = dg * 8;
    int tid = threadIdx.x;

    // zero the X planes (covers padding rows/cols)
    for (int idx = tid; idx < (8 * XPL) / 4; idx += 512)
        *(float4*)&sm[XOFF + idx * 4] = make_float4(0.f, 0.f, 0.f, 0.f);
    __syncthreads();

    // load qv slab into per-channel planes
    for (int idx = tid; idx < HW * 2; idx += 512) {
        int pos = idx >> 1;
        int q = (idx & 1) * 4;
        float4 v = *(const float4*)&g_qv[(size_t)(b * HW + pos) * D1 + dbase + q];
        int i = pos / N, j = pos % N;
        int base = i * XPIT + j;
        sm[XOFF + (q + 0) * XPL + base] = v.x;
        sm[XOFF + (q + 1) * XPL + base] = v.y;
        sm[XOFF + (q + 2) * XPL + base] = v.z;
        sm[XOFF + (q + 3) * XPL + base] = v.w;
    }
    // coefficient vectors: ap[d][k] = a[(k-63) mod 112][dbase+d]
    for (int idx = tid; idx < 8 * 128; idx += 512) {
        int dd = idx >> 7, k = idx & 127;
        int src = (k + 49) % TWO_N;
        sm[A1OFF + idx] = g_a[src * D1 + dbase + dd];
        sm[A2OFF + idx] = g_a[TWO_N * D1 + src * D1 + dbase + dd];
    }
    __syncthreads();

    int w = tid >> 5, lane = tid & 31;
    int d = w & 7, axis = w >> 3;
    int g = lane >> 2, t4 = lane & 3;
    float* X  = sm + XOFF + d * XPL;
    float* A1 = sm + A1OFF + d * 128;
    float* A2 = sm + A2OFF + d * 128;

    for (int h = 0; h < 2; h++) {
        int M0 = h * 32;
        float C[2][7][4];
#pragma unroll
        for (int mt = 0; mt < 2; mt++)
#pragma unroll
            for (int nt = 0; nt < 7; nt++)
#pragma unroll
                for (int r = 0; r < 4; r++) C[mt][nt][r] = 0.0f;

        if (axis == 0) {
            // o1[i][j] = sum_jp X[i][jp] * a1[(j-jp) mod 112]
            for (int kt = 0; kt < 8; kt++) {
                int k0 = kt * 8;
                uint32_t a[2][4];
#pragma unroll
                for (int mt = 0; mt < 2; mt++) {
                    int r0 = M0 + mt * 16;
                    a[mt][0] = to_tf32(X[(r0 + g) * XPIT + k0 + t4]);
                    a[mt][1] = to_tf32(X[(r0 + g + 8) * XPIT + k0 + t4]);
                    a[mt][2] = to_tf32(X[(r0 + g) * XPIT + k0 + t4 + 4]);
                    a[mt][3] = to_tf32(X[(r0 + g + 8) * XPIT + k0 + t4 + 4]);
                }
#pragma unroll
                for (int nt = 0; nt < 7; nt++) {
                    int idx0 = nt * 8 + g - k0 - t4 + 63;
                    uint32_t bb[2];
                    bb[0] = to_tf32(A1[idx0]);
                    bb[1] = to_tf32(A1[idx0 - 4]);
#pragma unroll
                    for (int mt = 0; mt < 2; mt++)
                        mma_tf32(C[mt][nt], a[mt], bb);
                }
            }
        } else {
            // o2[i][j] = sum_ip a2[(i-ip) mod 112] * X[ip][j]
            for (int kt = 0; kt < 8; kt++) {
                int k0 = kt * 8;
                uint32_t a[2][4];
#pragma unroll
                for (int mt = 0; mt < 2; mt++) {
                    int r0 = M0 + mt * 16;
                    a[mt][0] = to_tf32(A2[r0 + g - k0 - t4 + 63]);
                    a[mt][1] = to_tf32(A2[r0 + g + 8 - k0 - t4 + 63]);
                    a[mt][2] = to_tf32(A2[r0 + g - k0 - t4 - 4 + 63]);
                    a[mt][3] = to_tf32(A2[r0 + g + 8 - k0 - t4 - 4 + 63]);
                }
#pragma unroll
                for (int nt = 0; nt < 7; nt++) {
                    uint32_t bb[2];
                    bb[0] = to_tf32(X[(k0 + t4) * XPIT + nt * 8 + g]);
                    bb[1] = to_tf32(X[(k0 + t4 + 4) * XPIT + nt * 8 + g]);
#pragma unroll
                    for (int mt = 0; mt < 2; mt++)
                        mma_tf32(C[mt][nt], a[mt], bb);
                }
            }
        }
        __syncthreads();    // all compute (reads of X) done; res free from prior task

        float* R = sm + RESOFF + d * RPL;
        if (axis == 0) {
#pragma unroll
            for (int mt = 0; mt < 2; mt++) {
                int ia = M0 + mt * 16 + g;
                int ib = ia + 8;
#pragma unroll
                for (int nt = 0; nt < 7; nt++) {
                    int j = nt * 8 + 2 * t4;
                    if (ia < 56) {
                        R[(ia - M0) * RPIT + j]     = C[mt][nt][0];
                        R[(ia - M0) * RPIT + j + 1] = C[mt][nt][1];
                    }
                    if (ib < 56) {
                        R[(ib - M0) * RPIT + j]     = C[mt][nt][2];
                        R[(ib - M0) * RPIT + j + 1] = C[mt][nt][3];
                    }
                }
            }
        }
        __syncthreads();
        if (axis == 1) {
#pragma unroll
            for (int mt = 0; mt < 2; mt++) {
                int ia = M0 + mt * 16 + g;
                int ib = ia + 8;
#pragma unroll
                for (int nt = 0; nt < 7; nt++) {
                    int j = nt * 8 + 2 * t4;
                    if (ia < 56) {
                        R[(ia - M0) * RPIT + j]     += C[mt][nt][0];
                        R[(ia - M0) * RPIT + j + 1] += C[mt][nt][1];
                    }
                    if (ib < 56) {
                        R[(ib - M0) * RPIT + j]     += C[mt][nt][2];
                        R[(ib - M0) * RPIT + j + 1] += C[mt][nt][3];
                    }
                }
            }
        }
        __syncthreads();

        // gated coalesced store: g_t = g_p * (o1 + o2) for rows M0..M0+rows-1
        int rows = (h == 0) ? 32 : 24;
        for (int idx = tid; idx < rows * N * 2; idx += 512) {
            int pos = idx >> 1;
            int q = (idx & 1) * 4;
            int ir = pos / N, j = pos % N;
            size_t gidx = (size_t)(b * HW + (M0 + ir) * N + j) * D1 + dbase + q;
            float4 pv = *(const float4*)&g_p[gidx];
            int base = ir * RPIT + j;
            float4 o;
            o.x = pv.x * sm[RESOFF + (q + 0) * RPL + base];
            o.y = pv.y * sm[RESOFF + (q + 1) * RPL + base];
            o.z = pv.z * sm[RESOFF + (q + 2) * RPL + base];
            o.w = pv.w * sm[RESOFF + (q + 3) * RPL + base];
            *(float4*)&g_t[gidx] = o;
        }
        __syncthreads();
    }
}

// ---------------- kernel D: output GEMM (TF32 mma, 2-stage pipeline, 2 blocks/SM) ----------------
#define OBPITCH 72
#define OUT_SMEM ((2 * 32 * APITCH + 2 * 32 * OBPITCH) * 4)   // 53248 B
__global__ __launch_bounds__(256, 2) void out_gemm_kernel(
    const float* __restrict__ ow, const float* __restrict__ ob,
    float* __restrict__ out) {
    extern __shared__ float smem[];
    float (*As)[32][APITCH]  = (float (*)[32][APITCH])smem;
    float (*Bs)[32][OBPITCH] = (float (*)[32][OBPITCH])(smem + 2 * 32 * APITCH);

    int tid = threadIdx.x;
    int warp = tid >> 5, lane = tid & 31;
    int wm = (warp >> 1) * 32;
    int wn = (warp & 1) * 32;
    int quad = lane >> 2, tid4 = lane & 3;
    int m0 = blockIdx.y * 128, n0 = blockIdx.x * 64;

    int lrow = tid >> 1;
    int lcb  = (tid & 1) * 16;
    int wrow = tid >> 2;
    int wkb  = (tid & 3) * 8;

    float c[2][4][4];
#pragma unroll
    for (int i = 0; i < 2; i++)
#pragma unroll
        for (int j = 0; j < 4; j++)
#pragma unroll
            for (int r = 0; r < 4; r++) c[i][j][r] = 0.0f;

    float4 pa[4];
    float4 pb2[2];

#pragma unroll
    for (int v = 0; v < 4; v++)
        pa[v] = *(const float4*)&g_t[(size_t)(m0 + lrow) * D1 + lcb + v * 4];
    pb2[0] = *(const float4*)&ow[(n0 + wrow) * D1 + wkb];
    pb2[1] = *(const float4*)&ow[(n0 + wrow) * D1 + wkb + 4];
    {
#pragma unroll
        for (int v = 0; v < 4; v++) {
            As[0][lcb + v * 4 + 0][lrow] = __uint_as_float(to_tf32(pa[v].x));
            As[0][lcb + v * 4 + 1][lrow] = __uint_as_float(to_tf32(pa[v].y));
            As[0][lcb + v * 4 + 2][lrow] = __uint_as_float(to_tf32(pa[v].z));
            As[0][lcb + v * 4 + 3][lrow] = __uint_as_float(to_tf32(pa[v].w));
        }
        Bs[0][wkb + 0][wrow] = __uint_as_float(to_tf32(pb2[0].x));
        Bs[0][wkb + 1][wrow] = __uint_as_float(to_tf32(pb2[0].y));
        Bs[0][wkb + 2][wrow] = __uint_as_float(to_tf32(pb2[0].z));
        Bs[0][wkb + 3][wrow] = __uint_as_float(to_tf32(pb2[0].w));
        Bs[0][wkb + 4][wrow] = __uint_as_float(to_tf32(pb2[1].x));
        Bs[0][wkb + 5][wrow] = __uint_as_float(to_tf32(pb2[1].y));
        Bs[0][wkb + 6][wrow] = __uint_as_float(to_tf32(pb2[1].z));
        Bs[0][wkb + 7][wrow] = __uint_as_float(to_tf32(pb2[1].w));
    }
    __syncthreads();

    int s = 0;
    for (int kb = 0; kb < D1; kb += 32, s ^= 1) {
        bool hasNext = (kb + 32) < D1;
        if (hasNext) {
            int kn = kb + 32;
#pragma unroll
            for (int v = 0; v < 4; v++)
                pa[v] = *(const float4*)&g_t[(size_t)(m0 + lrow) * D1 + kn + lcb + v * 4];
            pb2[0] = *(const float4*)&ow[(n0 + wrow) * D1 + kn + wkb];
            pb2[1] = *(const float4*)&ow[(n0 + wrow) * D1 + kn + wkb + 4];
        }

#pragma unroll
        for (int k8 = 0; k8 < 32; k8 += 8) {
            uint32_t a[2][4];
#pragma unroll
            for (int mt = 0; mt < 2; mt++) {
                int mb = wm + mt * 16;
                a[mt][0] = __float_as_uint(As[s][k8 + tid4][mb + quad]);
                a[mt][1] = __float_as_uint(As[s][k8 + tid4][mb + quad + 8]);
                a[mt][2] = __float_as_uint(As[s][k8 + tid4 + 4][mb + quad]);
                a[mt][3] = __float_as_uint(As[s][k8 + tid4 + 4][mb + quad + 8]);
            }
#pragma unroll
            for (int nt = 0; nt < 4; nt++) {
                uint32_t b[2];
                int nb = wn + nt * 8 + quad;
                b[0] = __float_as_uint(Bs[s][k8 + tid4][nb]);
                b[1] = __float_as_uint(Bs[s][k8 + tid4 + 4][nb]);
#pragma unroll
                for (int mt = 0; mt < 2; mt++)
                    mma_tf32(c[mt][nt], a[mt], b);
            }
        }

        if (hasNext) {
            int ns = s ^ 1;
#pragma unroll
            for (int v = 0; v < 4; v++) {
                As[ns][lcb + v * 4 + 0][lrow] = __uint_as_float(to_tf32(pa[v].x));
                As[ns][lcb + v * 4 + 1][lrow] = __uint_as_float(to_tf32(pa[v].y));
                As[ns][lcb + v * 4 + 2][lrow] = __uint_as_float(to_tf32(pa[v].z));
                As[ns][lcb + v * 4 + 3][lrow] = __uint_as_float(to_tf32(pa[v].w));
            }
            Bs[ns][wkb + 0][wrow] = __uint_as_float(to_tf32(pb2[0].x));
            Bs[ns][wkb + 1][wrow] = __uint_as_float(to_tf32(pb2[0].y));
            Bs[ns][wkb + 2][wrow] = __uint_as_float(to_tf32(pb2[0].z));
            Bs[ns][wkb + 3][wrow] = __uint_as_float(to_tf32(pb2[0].w));
            Bs[ns][wkb + 4][wrow] = __uint_as_float(to_tf32(pb2[1].x));
            Bs[ns][wkb + 5][wrow] = __uint_as_float(to_tf32(pb2[1].y));
            Bs[ns][wkb + 6][wrow] = __uint_as_float(to_tf32(pb2[1].z));
            Bs[ns][wkb + 7][wrow] = __uint_as_float(to_tf32(pb2[1].w));
        }
        __syncthreads();
    }

#pragma unroll
    for (int mt = 0; mt < 2; mt++) {
#pragma unroll
        for (int half = 0; half < 2; half++) {
            int m = m0 + wm + mt * 16 + quad + half * 8;
#pragma unroll
            for (int nt = 0; nt < 4; nt++) {
                int n = n0 + wn + nt * 8 + tid4 * 2;
                float2 o = make_float2(c[mt][nt][half * 2 + 0] + ob[n],
                                       c[mt][nt][half * 2 + 1] + ob[n + 1]);
                *(float2*)&out[m * EMBED + n] = o;
            }
        }
    }
}

// ---------------- launch ----------------
extern "C" void kernel_launch(void* const* d_in, const int* in_sizes, int n_in,
                              void* d_out, int out_size) {
    const float* x    = (const float*)d_in[0];
    const float* p_w  = (const float*)d_in[1];
    const float* p_b  = (const float*)d_in[2];
    const float* q_w  = (const float*)d_in[3];
    const float* q_b  = (const float*)d_in[4];
    const float* v_w  = (const float*)d_in[5];
    const float* v_b  = (const float*)d_in[6];
    const float* o_w  = (const float*)d_in[7];
    const float* o_b  = (const float*)d_in[8];
    const float* slope = (const float*)d_in[9];
    const float* t1_w0 = (const float*)d_in[10];
    const float* t1_b0 = (const float*)d_in[11];
    const float* t1_ws = (const float*)d_in[12];
    const float* t1_bs = (const float*)d_in[13];
    const float* t1_wo = (const float*)d_in[14];
    const float* t1_bo = (const float*)d_in[15];
    const float* t2_w0 = (const float*)d_in[16];
    const float* t2_b0 = (const float*)d_in[17];
    const float* t2_ws = (const float*)d_in[18];
    const float* t2_bs = (const float*)d_in[19];
    const float* t2_wo = (const float*)d_in[20];
    const float* t2_bo = (const float*)d_in[21];
    float* out = (float*)d_out;

    static const int smemC = SMEMC_FLOATS * (int)sizeof(float);   // 217728 B
    cudaFuncSetAttribute(toeplitz_kernel, cudaFuncAttributeMaxDynamicSharedMemorySize, smemC);
    cudaFuncSetAttribute(pqv_kernel, cudaFuncAttributeMaxDynamicSharedMemorySize, PQV_SMEM);
    cudaFuncSetAttribute(out_gemm_kernel, cudaFuncAttributeMaxDynamicSharedMemorySize, OUT_SMEM);

    rpe_hidden_kernel<<<1, 256>>>(t1_w0, t1_b0, t1_ws, t1_bs, t2_w0, t2_b0, t2_ws, t2_bs);
    rpe_out_kernel<<<2 * TWO_N, 128>>>(t1_wo, t1_bo, t2_wo, t2_bo, slope);
    pqv_kernel<<<dim3(D1 / 32, TOK / 128), 256, PQV_SMEM>>>(x, p_w, p_b, q_w, q_b, v_w, v_b);
    toeplitz_kernel<<<dim3(D1 / 8, B), 512, smemC>>>();
    out_gemm_kernel<<<dim3(EMBED / 64, TOK / 128), 256, OUT_SMEM>>>(o_w, o_b, out);
}

// round 14
// speedup vs baseline: 1.8027x; 1.0849x over previous
#include <cuda_runtime.h>
#include <cuda_bf16.h>
#include <math.h>
#include <stdint.h>

#define B 8
#define N 56
#define HW 3136           // 56*56
#define TOK 25088         // 8*56*56
#define EMBED 192
#define D1 576
#define TWO_N 112
#define RPE_H 32

// ---------------- device scratch ----------------
__device__ float g_p[TOK * D1];
__device__ float g_qv[TOK * D1];    // tf32-rounded values (toeplitz-only consumer)
__device__ float g_t[TOK * D1];
__device__ float g_a[2 * TWO_N * D1];   // tf32-rounded (toeplitz-only consumer)
__device__ float g_h[2 * TWO_N * RPE_H];

__device__ __forceinline__ float silu_f(float x) {
    return __fdividef(x, 1.0f + __expf(-x));
}

__device__ __forceinline__ uint32_t to_tf32(float x) {
    uint32_t r;
    asm("cvt.rna.tf32.f32 %0, %1;" : "=r"(r) : "f"(x));
    return r;
}

__device__ __forceinline__ void mma_tf32(float c[4], const uint32_t a[4], const uint32_t b[2]) {
    asm volatile(
        "mma.sync.aligned.m16n8k8.row.col.f32.tf32.tf32.f32 "
        "{%0,%1,%2,%3}, {%4,%5,%6,%7}, {%8,%9}, {%0,%1,%2,%3};"
        : "+f"(c[0]), "+f"(c[1]), "+f"(c[2]), "+f"(c[3])
        : "r"(a[0]), "r"(a[1]), "r"(a[2]), "r"(a[3]), "r"(b[0]), "r"(b[1]));
}

// ---------------- kernel A1: RPE hidden layers ----------------
__global__ void rpe_hidden_kernel(const float* __restrict__ w0a, const float* __restrict__ b0a,
                                  const float* __restrict__ wsa, const float* __restrict__ bsa,
                                  const float* __restrict__ w0b, const float* __restrict__ b0b,
                                  const float* __restrict__ wsb, const float* __restrict__ bsb) {
    int t = threadIdx.x;
    int tno = t >> 7;
    int row = t & 127;
    if (row >= TWO_N) return;
    const float* W0 = tno ? w0b : w0a;
    const float* B0 = tno ? b0b : b0a;
    const float* WS = tno ? wsb : wsa;
    const float* BS = tno ? bsb : bsa;

    float tv;
    if (row == 0 || row == 56) tv = 0.0f;
    else if (row < 56) tv = (float)row;
    else tv = -(float)(row - 56);

    float h[RPE_H];
#pragma unroll
    for (int j = 0; j < RPE_H; j++) h[j] = tv * W0[j] + B0[j];

    for (int L = 0; L < 3; L++) {
        float hn[RPE_H];
#pragma unroll
        for (int j = 0; j < RPE_H; j++) {
            float s = BS[L * RPE_H + j];
#pragma unroll
            for (int k = 0; k < RPE_H; k++)
                s += fmaxf(h[k], 0.0f) * WS[L * RPE_H * RPE_H + j * RPE_H + k];
            hn[j] = s;
        }
#pragma unroll
        for (int j = 0; j < RPE_H; j++) h[j] = hn[j];
    }
#pragma unroll
    for (int k = 0; k < RPE_H; k++)
        g_h[(tno * TWO_N + row) * RPE_H + k] = fmaxf(h[k], 0.0f);
}

// ---------------- kernel A2: RPE output layer * decay (tf32-rounded output) ----------------
__global__ void rpe_out_kernel(const float* __restrict__ wo1, const float* __restrict__ bo1,
                               const float* __restrict__ wo2, const float* __restrict__ bo2,
                               const float* __restrict__ slope) {
    int bx = blockIdx.x;
    int tno = bx / TWO_N;
    int row = bx % TWO_N;
    const float* WO = tno ? wo2 : wo1;
    const float* BO = tno ? bo2 : bo1;

    __shared__ float hs[RPE_H];
    if (threadIdx.x < RPE_H)
        hs[threadIdx.x] = g_h[(tno * TWO_N + row) * RPE_H + threadIdx.x];
    __syncthreads();

    int e;
    if (row == 0 || row == 56) e = 0;
    else if (row < 56) e = row;
    else e = TWO_N - row;

    for (int d = threadIdx.x; d < D1; d += blockDim.x) {
        float s = BO[d];
#pragma unroll
        for (int k = 0; k < RPE_H; k++) s += hs[k] * WO[d * RPE_H + k];
        float sl = slope[d];
        sl = fminf(fmaxf(sl, 0.0f), 1.0f);
        sl = 0.95f + 0.05f * sl;
        float dec = (e == 0) ? 1.0f : __powf(sl, (float)e);
        g_a[(tno * TWO_N + row) * D1 + d] = __uint_as_float(to_tf32(s * dec));
    }
}

// ---------------- kernel B: fused p / q*v GEMMs (TF32 mma, 2-stage pipeline, BN=32) ----------------
#define APITCH 136   // ≡ 8 mod 32 -> conflict-free frag loads
#define BPITCH 40    // ≡ 8 mod 32
#define PQV_SMEM ((2 * 32 * APITCH + 2 * 3 * 32 * BPITCH) * 4)   // 65536 B

__global__ __launch_bounds__(256, 2) void pqv_kernel(
    const float* __restrict__ x,
    const float* __restrict__ pw, const float* __restrict__ pb,
    const float* __restrict__ qw, const float* __restrict__ qb,
    const float* __restrict__ vw, const float* __restrict__ vb) {
    extern __shared__ float smem[];
    float (*As)[32][APITCH]    = (float (*)[32][APITCH])smem;
    float (*Bs)[3][32][BPITCH] = (float (*)[3][32][BPITCH])(smem + 2 * 32 * APITCH);

    int tid = threadIdx.x;
    int warp = tid >> 5, lane = tid & 31;
    int wm = (warp >> 1) * 32;
    int wn = (warp & 1) * 16;
    int quad = lane >> 2, tid4 = lane & 3;
    int m0 = blockIdx.y * 128, n0 = blockIdx.x * 32;

    int lrow = tid >> 1;
    int lcb  = (tid & 1) * 16;
    int wrow = tid >> 3;
    int wkb  = (tid & 7) * 4;

    const float* wmats[3] = {pw, qw, vw};

    float c[3][2][2][4];
#pragma unroll
    for (int mt2 = 0; mt2 < 3; mt2++)
#pragma unroll
        for (int i = 0; i < 2; i++)
#pragma unroll
            for (int j = 0; j < 2; j++)
#pragma unroll
                for (int r = 0; r < 4; r++) c[mt2][i][j][r] = 0.0f;

    float4 pa[4];
    float4 pwv[3];

#pragma unroll
    for (int v = 0; v < 4; v++)
        pa[v] = *(const float4*)&x[(m0 + lrow) * EMBED + lcb + v * 4];
#pragma unroll
    for (int mat = 0; mat < 3; mat++)
        pwv[mat] = *(const float4*)&wmats[mat][(n0 + wrow) * EMBED + wkb];
    {
#pragma unroll
        for (int v = 0; v < 4; v++) {
            As[0][lcb + v * 4 + 0][lrow] = __uint_as_float(to_tf32(pa[v].x));
            As[0][lcb + v * 4 + 1][lrow] = __uint_as_float(to_tf32(pa[v].y));
            As[0][lcb + v * 4 + 2][lrow] = __uint_as_float(to_tf32(pa[v].z));
            As[0][lcb + v * 4 + 3][lrow] = __uint_as_float(to_tf32(pa[v].w));
        }
#pragma unroll
        for (int mat = 0; mat < 3; mat++) {
            Bs[0][mat][wkb + 0][wrow] = __uint_as_float(to_tf32(pwv[mat].x));
            Bs[0][mat][wkb + 1][wrow] = __uint_as_float(to_tf32(pwv[mat].y));
            Bs[0][mat][wkb + 2][wrow] = __uint_as_float(to_tf32(pwv[mat].z));
            Bs[0][mat][wkb + 3][wrow] = __uint_as_float(to_tf32(pwv[mat].w));
        }
    }
    __syncthreads();

    int s = 0;
    for (int kb = 0; kb < EMBED; kb += 32, s ^= 1) {
        bool hasNext = (kb + 32) < EMBED;
        if (hasNext) {
            int kn = kb + 32;
#pragma unroll
            for (int v = 0; v < 4; v++)
                pa[v] = *(const float4*)&x[(m0 + lrow) * EMBED + kn + lcb + v * 4];
#pragma unroll
            for (int mat = 0; mat < 3; mat++)
                pwv[mat] = *(const float4*)&wmats[mat][(n0 + wrow) * EMBED + kn + wkb];
        }

#pragma unroll
        for (int k8 = 0; k8 < 32; k8 += 8) {
            uint32_t a[2][4];
#pragma unroll
            for (int mt = 0; mt < 2; mt++) {
                int mb = wm + mt * 16;
                a[mt][0] = __float_as_uint(As[s][k8 + tid4][mb + quad]);
                a[mt][1] = __float_as_uint(As[s][k8 + tid4][mb + quad + 8]);
                a[mt][2] = __float_as_uint(As[s][k8 + tid4 + 4][mb + quad]);
                a[mt][3] = __float_as_uint(As[s][k8 + tid4 + 4][mb + quad + 8]);
            }
#pragma unroll
            for (int mat = 0; mat < 3; mat++) {
#pragma unroll
                for (int nt = 0; nt < 2; nt++) {
                    uint32_t b[2];
                    int nb = wn + nt * 8 + quad;
                    b[0] = __float_as_uint(Bs[s][mat][k8 + tid4][nb]);
                    b[1] = __float_as_uint(Bs[s][mat][k8 + tid4 + 4][nb]);
#pragma unroll
                    for (int mt = 0; mt < 2; mt++)
                        mma_tf32(c[mat][mt][nt], a[mt], b);
                }
            }
        }

        if (hasNext) {
            int ns = s ^ 1;
#pragma unroll
            for (int v = 0; v < 4; v++) {
                As[ns][lcb + v * 4 + 0][lrow] = __uint_as_float(to_tf32(pa[v].x));
                As[ns][lcb + v * 4 + 1][lrow] = __uint_as_float(to_tf32(pa[v].y));
                As[ns][lcb + v * 4 + 2][lrow] = __uint_as_float(to_tf32(pa[v].z));
                As[ns][lcb + v * 4 + 3][lrow] = __uint_as_float(to_tf32(pa[v].w));
            }
#pragma unroll
            for (int mat = 0; mat < 3; mat++) {
                Bs[ns][mat][wkb + 0][wrow] = __uint_as_float(to_tf32(pwv[mat].x));
                Bs[ns][mat][wkb + 1][wrow] = __uint_as_float(to_tf32(pwv[mat].y));
                Bs[ns][mat][wkb + 2][wrow] = __uint_as_float(to_tf32(pwv[mat].z));
                Bs[ns][mat][wkb + 3][wrow] = __uint_as_float(to_tf32(pwv[mat].w));
            }
        }
        __syncthreads();
    }

    // epilogue: p = silu(P); qv = silu(Q)*silu(V) stored tf32-rounded
    // (toeplitz is the only consumer and would cvt.rna these values anyway -> bit-identical)
#pragma unroll
    for (int mt = 0; mt < 2; mt++) {
#pragma unroll
        for (int half = 0; half < 2; half++) {
            int m = m0 + wm + mt * 16 + quad + half * 8;
#pragma unroll
            for (int nt = 0; nt < 2; nt++) {
                int n = n0 + wn + nt * 8 + tid4 * 2;
                float cp0 = c[0][mt][nt][half * 2 + 0] + pb[n];
                float cp1 = c[0][mt][nt][half * 2 + 1] + pb[n + 1];
                float cq0 = c[1][mt][nt][half * 2 + 0] + qb[n];
                float cq1 = c[1][mt][nt][half * 2 + 1] + qb[n + 1];
                float cv0 = c[2][mt][nt][half * 2 + 0] + vb[n];
                float cv1 = c[2][mt][nt][half * 2 + 1] + vb[n + 1];
                float2 pv = make_float2(silu_f(cp0), silu_f(cp1));
                float qv0 = silu_f(cq0) * silu_f(cv0);
                float qv1 = silu_f(cq1) * silu_f(cv1);
                float2 qv = make_float2(__uint_as_float(to_tf32(qv0)),
                                        __uint_as_float(to_tf32(qv1)));
                *(float2*)&g_p[m * D1 + n] = pv;
                *(float2*)&g_qv[m * D1 + n] = qv;
            }
        }
    }
}

// ---------------- kernel C: axial Toeplitz + gate (TF32 mma, merged axes per warp) ----------------
// Block = (b, 8-channel group), 512 threads = 16 warps.
// Warp w: channel d = w&7, row-half = w>>3 (rows M0..M0+31, M0 = half*32).
// Each warp accumulates BOTH o1 (X·A1 along width) and o2 (A2·X along height)
// into the same C fragments, then writes res into the (now dead) X plane area.
// g_qv / g_a are pre-rounded to tf32 -> no cvt in the mainloop, pure LDS+mma.
#define XPL   4608    // plane: 64 rows * 72
#define XPIT  72
#define RPIT  60      // res pitch within reused X plane
#define XOFF  0
#define A1OFF (8 * XPL)            // 36864
#define A2OFF (A1OFF + 8 * 128)    // 37888
#define SMEMC_FLOATS (A2OFF + 8 * 128)   // 38912 floats = 155648 B

__global__ __launch_bounds__(512, 1) void toeplitz_kernel() {
    extern __shared__ float sm[];

    int dg = blockIdx.x;                    // 0..71
    int b  = blockIdx.y;                    // 0..7
    int dbase = dg * 8;
    int tid = threadIdx.x;

    // zero the X planes (covers padding rows/cols)
    for (int idx = tid; idx < (8 * XPL) / 4; idx += 512)
        *(float4*)&sm[XOFF + idx * 4] = make_float4(0.f, 0.f, 0.f, 0.f);
    __syncthreads();

    // load qv slab into per-channel planes (values already tf32-rounded)
    for (int idx = tid; idx < HW * 2; idx += 512) {
        int pos = idx >> 1;
        int q = (idx & 1) * 4;
        float4 v = *(const float4*)&g_qv[(size_t)(b * HW + pos) * D1 + dbase + q];
        int i = pos / N, j = pos % N;
        int base = i * XPIT + j;
        sm[XOFF + (q + 0) * XPL + base] = v.x;
        sm[XOFF + (q + 1) * XPL + base] = v.y;
        sm[XOFF + (q + 2) * XPL + base] = v.z;
        sm[XOFF + (q + 3) * XPL + base] = v.w;
    }
    // coefficient vectors: ap[d][k] = a[(k-63) mod 112][dbase+d] (tf32-rounded)
    for (int idx = tid; idx < 8 * 128; idx += 512) {
        int dd = idx >> 7, k = idx & 127;
        int src = (k + 49) % TWO_N;
        sm[A1OFF + idx] = g_a[src * D1 + dbase + dd];
        sm[A2OFF + idx] = g_a[TWO_N * D1 + src * D1 + dbase + dd];
    }
    __syncthreads();

    int w = tid >> 5, lane = tid & 31;
    int d = w & 7, half = w >> 3;
    int g = lane >> 2, t4 = lane & 3;
    float* X  = sm + XOFF + d * XPL;
    float* A1 = sm + A1OFF + d * 128;
    float* A2 = sm + A2OFF + d * 128;
    int M0 = half * 32;

    float C[2][7][4];
#pragma unroll
    for (int mt = 0; mt < 2; mt++)
#pragma unroll
        for (int nt = 0; nt < 7; nt++)
#pragma unroll
            for (int r = 0; r < 4; r++) C[mt][nt][r] = 0.0f;

    // ---- o1[i][j] = sum_jp X[i][jp] * a1[(j-jp) mod 112] ----
    for (int kt = 0; kt < 8; kt++) {
        int k0 = kt * 8;
        uint32_t a[2][4];
#pragma unroll
        for (int mt = 0; mt < 2; mt++) {
            int r0 = M0 + mt * 16;
            a[mt][0] = __float_as_uint(X[(r0 + g) * XPIT + k0 + t4]);
            a[mt][1] = __float_as_uint(X[(r0 + g + 8) * XPIT + k0 + t4]);
            a[mt][2] = __float_as_uint(X[(r0 + g) * XPIT + k0 + t4 + 4]);
            a[mt][3] = __float_as_uint(X[(r0 + g + 8) * XPIT + k0 + t4 + 4]);
        }
#pragma unroll
        for (int nt = 0; nt < 7; nt++) {
            int idx0 = nt * 8 + g - k0 - t4 + 63;
            uint32_t bb[2];
            bb[0] = __float_as_uint(A1[idx0]);
            bb[1] = __float_as_uint(A1[idx0 - 4]);
#pragma unroll
            for (int mt = 0; mt < 2; mt++)
                mma_tf32(C[mt][nt], a[mt], bb);
        }
    }
    // ---- o2[i][j] = sum_ip a2[(i-ip) mod 112] * X[ip][j] (same C accumulators) ----
    for (int kt = 0; kt < 8; kt++) {
        int k0 = kt * 8;
        uint32_t a[2][4];
#pragma unroll
        for (int mt = 0; mt < 2; mt++) {
            int r0 = M0 + mt * 16;
            a[mt][0] = __float_as_uint(A2[r0 + g - k0 - t4 + 63]);
            a[mt][1] = __float_as_uint(A2[r0 + g + 8 - k0 - t4 + 63]);
            a[mt][2] = __float_as_uint(A2[r0 + g - k0 - t4 - 4 + 63]);
            a[mt][3] = __float_as_uint(A2[r0 + g + 8 - k0 - t4 - 4 + 63]);
        }
#pragma unroll
        for (int nt = 0; nt < 7; nt++) {
            uint32_t bb[2];
            bb[0] = __float_as_uint(X[(k0 + t4) * XPIT + nt * 8 + g]);
            bb[1] = __float_as_uint(X[(k0 + t4 + 4) * XPIT + nt * 8 + g]);
#pragma unroll
            for (int mt = 0; mt < 2; mt++)
                mma_tf32(C[mt][nt], a[mt], bb);
        }
    }
    __syncthreads();    // all X reads done -> X planes reusable as res buffer

    // write res (o1+o2) into reused X plane area: res[d][row][j] at d*XPL + row*RPIT + j
    {
        float* R = sm + XOFF + d * XPL;
#pragma unroll
        for (int mt = 0; mt < 2; mt++) {
            int ia = M0 + mt * 16 + g;
            int ib = ia + 8;
#pragma unroll
            for (int nt = 0; nt < 7; nt++) {
                int j = nt * 8 + 2 * t4;
                if (ia < 56) {
                    R[ia * RPIT + j]     = C[mt][nt][0];
                    R[ia * RPIT + j + 1] = C[mt][nt][1];
                }
                if (ib < 56) {
                    R[ib * RPIT + j]     = C[mt][nt][2];
                    R[ib * RPIT + j + 1] = C[mt][nt][3];
                }
            }
        }
    }
    __syncthreads();

    // gated coalesced store: g_t = g_p * (o1 + o2), all 56 rows
    for (int idx = tid; idx < HW * 2; idx += 512) {
        int pos = idx >> 1;
        int q = (idx & 1) * 4;
        int ir = pos / N, j = pos % N;
        size_t gidx = (size_t)(b * HW + pos) * D1 + dbase + q;
        float4 pv = *(const float4*)&g_p[gidx];
        int base = ir * RPIT + j;
        float4 o;
        o.x = pv.x * sm[XOFF + (q + 0) * XPL + base];
        o.y = pv.y * sm[XOFF + (q + 1) * XPL + base];
        o.z = pv.z * sm[XOFF + (q + 2) * XPL + base];
        o.w = pv.w * sm[XOFF + (q + 3) * XPL + base];
        *(float4*)&g_t[gidx] = o;
    }
}

// ---------------- kernel D: output GEMM (TF32 mma, 2-stage pipeline, 2 blocks/SM) ----------------
#define OBPITCH 72
#define OUT_SMEM ((2 * 32 * APITCH + 2 * 32 * OBPITCH) * 4)   // 53248 B
__global__ __launch_bounds__(256, 2) void out_gemm_kernel(
    const float* __restrict__ ow, const float* __restrict__ ob,
    float* __restrict__ out) {
    extern __shared__ float smem[];
    float (*As)[32][APITCH]  = (float (*)[32][APITCH])smem;
    float (*Bs)[32][OBPITCH] = (float (*)[32][OBPITCH])(smem + 2 * 32 * APITCH);

    int tid = threadIdx.x;
    int warp = tid >> 5, lane = tid & 31;
    int wm = (warp >> 1) * 32;
    int wn = (warp & 1) * 32;
    int quad = lane >> 2, tid4 = lane & 3;
    int m0 = blockIdx.y * 128, n0 = blockIdx.x * 64;

    int lrow = tid >> 1;
    int lcb  = (tid & 1) * 16;
    int wrow = tid >> 2;
    int wkb  = (tid & 3) * 8;

    float c[2][4][4];
#pragma unroll
    for (int i = 0; i < 2; i++)
#pragma unroll
        for (int j = 0; j < 4; j++)
#pragma unroll
            for (int r = 0; r < 4; r++) c[i][j][r] = 0.0f;

    float4 pa[4];
    float4 pb2[2];

#pragma unroll
    for (int v = 0; v < 4; v++)
        pa[v] = *(const float4*)&g_t[(size_t)(m0 + lrow) * D1 + lcb + v * 4];
    pb2[0] = *(const float4*)&ow[(n0 + wrow) * D1 + wkb];
    pb2[1] = *(const float4*)&ow[(n0 + wrow) * D1 + wkb + 4];
    {
#pragma unroll
        for (int v = 0; v < 4; v++) {
            As[0][lcb + v * 4 + 0][lrow] = __uint_as_float(to_tf32(pa[v].x));
            As[0][lcb + v * 4 + 1][lrow] = __uint_as_float(to_tf32(pa[v].y));
            As[0][lcb + v * 4 + 2][lrow] = __uint_as_float(to_tf32(pa[v].z));
            As[0][lcb + v * 4 + 3][lrow] = __uint_as_float(to_tf32(pa[v].w));
        }
        Bs[0][wkb + 0][wrow] = __uint_as_float(to_tf32(pb2[0].x));
        Bs[0][wkb + 1][wrow] = __uint_as_float(to_tf32(pb2[0].y));
        Bs[0][wkb + 2][wrow] = __uint_as_float(to_tf32(pb2[0].z));
        Bs[0][wkb + 3][wrow] = __uint_as_float(to_tf32(pb2[0].w));
        Bs[0][wkb + 4][wrow] = __uint_as_float(to_tf32(pb2[1].x));
        Bs[0][wkb + 5][wrow] = __uint_as_float(to_tf32(pb2[1].y));
        Bs[0][wkb + 6][wrow] = __uint_as_float(to_tf32(pb2[1].z));
        Bs[0][wkb + 7][wrow] = __uint_as_float(to_tf32(pb2[1].w));
    }
    __syncthreads();

    int s = 0;
    for (int kb = 0; kb < D1; kb += 32, s ^= 1) {
        bool hasNext = (kb + 32) < D1;
        if (hasNext) {
            int kn = kb + 32;
#pragma unroll
            for (int v = 0; v < 4; v++)
                pa[v] = *(const float4*)&g_t[(size_t)(m0 + lrow) * D1 + kn + lcb + v * 4];
            pb2[0] = *(const float4*)&ow[(n0 + wrow) * D1 + kn + wkb];
            pb2[1] = *(const float4*)&ow[(n0 + wrow) * D1 + kn + wkb + 4];
        }

#pragma unroll
        for (int k8 = 0; k8 < 32; k8 += 8) {
            uint32_t a[2][4];
#pragma unroll
            for (int mt = 0; mt < 2; mt++) {
                int mb = wm + mt * 16;
                a[mt][0] = __float_as_uint(As[s][k8 + tid4][mb + quad]);
                a[mt][1] = __float_as_uint(As[s][k8 + tid4][mb + quad + 8]);
                a[mt][2] = __float_as_uint(As[s][k8 + tid4 + 4][mb + quad]);
                a[mt][3] = __float_as_uint(As[s][k8 + tid4 + 4][mb + quad + 8]);
            }
#pragma unroll
            for (int nt = 0; nt < 4; nt++) {
                uint32_t b[2];
                int nb = wn + nt * 8 + quad;
                b[0] = __float_as_uint(Bs[s][k8 + tid4][nb]);
                b[1] = __float_as_uint(Bs[s][k8 + tid4 + 4][nb]);
#pragma unroll
                for (int mt = 0; mt < 2; mt++)
                    mma_tf32(c[mt][nt], a[mt], b);
            }
        }

        if (hasNext) {
            int ns = s ^ 1;
#pragma unroll
            for (int v = 0; v < 4; v++) {
                As[ns][lcb + v * 4 + 0][lrow] = __uint_as_float(to_tf32(pa[v].x));
                As[ns][lcb + v * 4 + 1][lrow] = __uint_as_float(to_tf32(pa[v].y));
                As[ns][lcb + v * 4 + 2][lrow] = __uint_as_float(to_tf32(pa[v].z));
                As[ns][lcb + v * 4 + 3][lrow] = __uint_as_float(to_tf32(pa[v].w));
            }
            Bs[ns][wkb + 0][wrow] = __uint_as_float(to_tf32(pb2[0].x));
            Bs[ns][wkb + 1][wrow] = __uint_as_float(to_tf32(pb2[0].y));
            Bs[ns][wkb + 2][wrow] = __uint_as_float(to_tf32(pb2[0].z));
            Bs[ns][wkb + 3][wrow] = __uint_as_float(to_tf32(pb2[0].w));
            Bs[ns][wkb + 4][wrow] = __uint_as_float(to_tf32(pb2[1].x));
            Bs[ns][wkb + 5][wrow] = __uint_as_float(to_tf32(pb2[1].y));
            Bs[ns][wkb + 6][wrow] = __uint_as_float(to_tf32(pb2[1].z));
            Bs[ns][wkb + 7][wrow] = __uint_as_float(to_tf32(pb2[1].w));
        }
        __syncthreads();
    }

#pragma unroll
    for (int mt = 0; mt < 2; mt++) {
#pragma unroll
        for (int half = 0; half < 2; half++) {
            int m = m0 + wm + mt * 16 + quad + half * 8;
#pragma unroll
            for (int nt = 0; nt < 4; nt++) {
                int n = n0 + wn + nt * 8 + tid4 * 2;
                float2 o = make_float2(c[mt][nt][half * 2 + 0] + ob[n],
                                       c[mt][nt][half * 2 + 1] + ob[n + 1]);
                *(float2*)&out[m * EMBED + n] = o;
            }
        }
    }
}

// ---------------- launch ----------------
extern "C" void kernel_launch(void* const* d_in, const int* in_sizes, int n_in,
                              void* d_out, int out_size) {
    const float* x    = (const float*)d_in[0];
    const float* p_w  = (const float*)d_in[1];
    const float* p_b  = (const float*)d_in[2];
    const float* q_w  = (const float*)d_in[3];
    const float* q_b  = (const float*)d_in[4];
    const float* v_w  = (const float*)d_in[5];
    const float* v_b  = (const float*)d_in[6];
    const float* o_w  = (const float*)d_in[7];
    const float* o_b  = (const float*)d_in[8];
    const float* slope = (const float*)d_in[9];
    const float* t1_w0 = (const float*)d_in[10];
    const float* t1_b0 = (const float*)d_in[11];
    const float* t1_ws = (const float*)d_in[12];
    const float* t1_bs = (const float*)d_in[13];
    const float* t1_wo = (const float*)d_in[14];
    const float* t1_bo = (const float*)d_in[15];
    const float* t2_w0 = (const float*)d_in[16];
    const float* t2_b0 = (const float*)d_in[17];
    const float* t2_ws = (const float*)d_in[18];
    const float* t2_bs = (const float*)d_in[19];
    const float* t2_wo = (const float*)d_in[20];
    const float* t2_bo = (const float*)d_in[21];
    float* out = (float*)d_out;

    static const int smemC = SMEMC_FLOATS * (int)sizeof(float);   // 155648 B
    cudaFuncSetAttribute(toeplitz_kernel, cudaFuncAttributeMaxDynamicSharedMemorySize, smemC);
    cudaFuncSetAttribute(pqv_kernel, cudaFuncAttributeMaxDynamicSharedMemorySize, PQV_SMEM);
    cudaFuncSetAttribute(out_gemm_kernel, cudaFuncAttributeMaxDynamicSharedMemorySize, OUT_SMEM);

    rpe_hidden_kernel<<<1, 256>>>(t1_w0, t1_b0, t1_ws, t1_bs, t2_w0, t2_b0, t2_ws, t2_bs);
    rpe_out_kernel<<<2 * TWO_N, 128>>>(t1_wo, t1_bo, t2_wo, t2_bo, slope);
    pqv_kernel<<<dim3(D1 / 32, TOK / 128), 256, PQV_SMEM>>>(x, p_w, p_b, q_w, q_b, v_w, v_b);
    toeplitz_kernel<<<dim3(D1 / 8, B), 512, smemC>>>();
    out_gemm_kernel<<<dim3(EMBED / 64, TOK / 128), 256, OUT_SMEM>>>(o_w, o_b, out);
}

// round 15
// speedup vs baseline: 1.8917x; 1.0494x over previous
#include <cuda_runtime.h>
#include <cuda_bf16.h>
#include <math.h>
#include <stdint.h>

#define B 8
#define N 56
#define HW 3136           // 56*56
#define TOK 25088         // 8*56*56
#define EMBED 192
#define D1 576
#define TWO_N 112
#define RPE_H 32

// ---------------- device scratch ----------------
__device__ float g_p[TOK * D1];
__device__ float g_qv[TOK * D1];    // tf32-rounded values (toeplitz-only consumer)
__device__ float g_t[TOK * D1];
__device__ float g_a[2 * TWO_N * D1];   // tf32-rounded (toeplitz-only consumer)

__device__ __forceinline__ float silu_f(float x) {
    return __fdividef(x, 1.0f + __expf(-x));
}

__device__ __forceinline__ uint32_t to_tf32(float x) {
    uint32_t r;
    asm("cvt.rna.tf32.f32 %0, %1;" : "=r"(r) : "f"(x));
    return r;
}

__device__ __forceinline__ void mma_tf32(float c[4], const uint32_t a[4], const uint32_t b[2]) {
    asm volatile(
        "mma.sync.aligned.m16n8k8.row.col.f32.tf32.tf32.f32 "
        "{%0,%1,%2,%3}, {%4,%5,%6,%7}, {%8,%9}, {%0,%1,%2,%3};"
        : "+f"(c[0]), "+f"(c[1]), "+f"(c[2]), "+f"(c[3])
        : "r"(a[0]), "r"(a[1]), "r"(a[2]), "r"(a[3]), "r"(b[0]), "r"(b[1]));
}

// ---------------- kernel A: RPE (hidden MLP + output layer + decay, merged) ----------------
// One block per (tno, row). Warp 0 computes the 32-wide hidden chain cooperatively
// (identical FMA order to the original two-kernel version -> bit-identical g_a).
__global__ void rpe_kernel(const float* __restrict__ w0a, const float* __restrict__ b0a,
                           const float* __restrict__ wsa, const float* __restrict__ bsa,
                           const float* __restrict__ wo1, const float* __restrict__ bo1,
                           const float* __restrict__ w0b, const float* __restrict__ b0b,
                           const float* __restrict__ wsb, const float* __restrict__ bsb,
                           const float* __restrict__ wo2, const float* __restrict__ bo2,
                           const float* __restrict__ slope) {
    int bx = blockIdx.x;            // 0..223
    int tno = bx / TWO_N;
    int row = bx % TWO_N;
    const float* W0 = tno ? w0b : w0a;
    const float* B0 = tno ? b0b : b0a;
    const float* WS = tno ? wsb : wsa;
    const float* BS = tno ? bsb : bsa;
    const float* WO = tno ? wo2 : wo1;
    const float* BO = tno ? bo2 : bo1;

    __shared__ float hs[RPE_H];
    int lane = threadIdx.x;

    if (lane < RPE_H) {
        float tv;
        if (row == 0 || row == 56) tv = 0.0f;
        else if (row < 56) tv = (float)row;
        else tv = -(float)(row - 56);

        float h = tv * W0[lane] + B0[lane];
        hs[lane] = h;
        __syncwarp();
        for (int L = 0; L < 3; L++) {
            float s = BS[L * RPE_H + lane];
#pragma unroll
            for (int k = 0; k < RPE_H; k++)
                s += fmaxf(hs[k], 0.0f) * WS[L * RPE_H * RPE_H + lane * RPE_H + k];
            __syncwarp();
            hs[lane] = s;
            __syncwarp();
        }
        hs[lane] = fmaxf(hs[lane], 0.0f);
    }
    __syncthreads();

    int e;
    if (row == 0 || row == 56) e = 0;
    else if (row < 56) e = row;
    else e = TWO_N - row;

    for (int d = threadIdx.x; d < D1; d += blockDim.x) {
        float s = BO[d];
#pragma unroll
        for (int k = 0; k < RPE_H; k++) s += hs[k] * WO[d * RPE_H + k];
        float sl = slope[d];
        sl = fminf(fmaxf(sl, 0.0f), 1.0f);
        sl = 0.95f + 0.05f * sl;
        float dec = (e == 0) ? 1.0f : __powf(sl, (float)e);
        g_a[(tno * TWO_N + row) * D1 + d] = __uint_as_float(to_tf32(s * dec));
    }
}

// ---------------- kernel B: fused p / q*v GEMMs (TF32 mma, 2-stage pipeline, BN=32) ----------------
#define APITCH 136   // ≡ 8 mod 32 -> conflict-free frag loads
#define BPITCH 40    // ≡ 8 mod 32
#define PQV_SMEM ((2 * 32 * APITCH + 2 * 3 * 32 * BPITCH) * 4)   // 65536 B

__global__ __launch_bounds__(256, 2) void pqv_kernel(
    const float* __restrict__ x,
    const float* __restrict__ pw, const float* __restrict__ pb,
    const float* __restrict__ qw, const float* __restrict__ qb,
    const float* __restrict__ vw, const float* __restrict__ vb) {
    extern __shared__ float smem[];
    float (*As)[32][APITCH]    = (float (*)[32][APITCH])smem;
    float (*Bs)[3][32][BPITCH] = (float (*)[3][32][BPITCH])(smem + 2 * 32 * APITCH);

    int tid = threadIdx.x;
    int warp = tid >> 5, lane = tid & 31;
    int wm = (warp >> 1) * 32;
    int wn = (warp & 1) * 16;
    int quad = lane >> 2, tid4 = lane & 3;
    int m0 = blockIdx.y * 128, n0 = blockIdx.x * 32;

    int lrow = tid >> 1;
    int lcb  = (tid & 1) * 16;
    int wrow = tid >> 3;
    int wkb  = (tid & 7) * 4;

    const float* wmats[3] = {pw, qw, vw};

    float c[3][2][2][4];
#pragma unroll
    for (int mt2 = 0; mt2 < 3; mt2++)
#pragma unroll
        for (int i = 0; i < 2; i++)
#pragma unroll
            for (int j = 0; j < 2; j++)
#pragma unroll
                for (int r = 0; r < 4; r++) c[mt2][i][j][r] = 0.0f;

    float4 pa[4];
    float4 pwv[3];

#pragma unroll
    for (int v = 0; v < 4; v++)
        pa[v] = *(const float4*)&x[(m0 + lrow) * EMBED + lcb + v * 4];
#pragma unroll
    for (int mat = 0; mat < 3; mat++)
        pwv[mat] = *(const float4*)&wmats[mat][(n0 + wrow) * EMBED + wkb];
    {
#pragma unroll
        for (int v = 0; v < 4; v++) {
            As[0][lcb + v * 4 + 0][lrow] = __uint_as_float(to_tf32(pa[v].x));
            As[0][lcb + v * 4 + 1][lrow] = __uint_as_float(to_tf32(pa[v].y));
            As[0][lcb + v * 4 + 2][lrow] = __uint_as_float(to_tf32(pa[v].z));
            As[0][lcb + v * 4 + 3][lrow] = __uint_as_float(to_tf32(pa[v].w));
        }
#pragma unroll
        for (int mat = 0; mat < 3; mat++) {
            Bs[0][mat][wkb + 0][wrow] = __uint_as_float(to_tf32(pwv[mat].x));
            Bs[0][mat][wkb + 1][wrow] = __uint_as_float(to_tf32(pwv[mat].y));
            Bs[0][mat][wkb + 2][wrow] = __uint_as_float(to_tf32(pwv[mat].z));
            Bs[0][mat][wkb + 3][wrow] = __uint_as_float(to_tf32(pwv[mat].w));
        }
    }
    __syncthreads();

    int s = 0;
    for (int kb = 0; kb < EMBED; kb += 32, s ^= 1) {
        bool hasNext = (kb + 32) < EMBED;
        if (hasNext) {
            int kn = kb + 32;
#pragma unroll
            for (int v = 0; v < 4; v++)
                pa[v] = *(const float4*)&x[(m0 + lrow) * EMBED + kn + lcb + v * 4];
#pragma unroll
            for (int mat = 0; mat < 3; mat++)
                pwv[mat] = *(const float4*)&wmats[mat][(n0 + wrow) * EMBED + kn + wkb];
        }

#pragma unroll
        for (int k8 = 0; k8 < 32; k8 += 8) {
            uint32_t a[2][4];
#pragma unroll
            for (int mt = 0; mt < 2; mt++) {
                int mb = wm + mt * 16;
                a[mt][0] = __float_as_uint(As[s][k8 + tid4][mb + quad]);
                a[mt][1] = __float_as_uint(As[s][k8 + tid4][mb + quad + 8]);
                a[mt][2] = __float_as_uint(As[s][k8 + tid4 + 4][mb + quad]);
                a[mt][3] = __float_as_uint(As[s][k8 + tid4 + 4][mb + quad + 8]);
            }
#pragma unroll
            for (int mat = 0; mat < 3; mat++) {
#pragma unroll
                for (int nt = 0; nt < 2; nt++) {
                    uint32_t b[2];
                    int nb = wn + nt * 8 + quad;
                    b[0] = __float_as_uint(Bs[s][mat][k8 + tid4][nb]);
                    b[1] = __float_as_uint(Bs[s][mat][k8 + tid4 + 4][nb]);
#pragma unroll
                    for (int mt = 0; mt < 2; mt++)
                        mma_tf32(c[mat][mt][nt], a[mt], b);
                }
            }
        }

        if (hasNext) {
            int ns = s ^ 1;
#pragma unroll
            for (int v = 0; v < 4; v++) {
                As[ns][lcb + v * 4 + 0][lrow] = __uint_as_float(to_tf32(pa[v].x));
                As[ns][lcb + v * 4 + 1][lrow] = __uint_as_float(to_tf32(pa[v].y));
                As[ns][lcb + v * 4 + 2][lrow] = __uint_as_float(to_tf32(pa[v].z));
                As[ns][lcb + v * 4 + 3][lrow] = __uint_as_float(to_tf32(pa[v].w));
            }
#pragma unroll
            for (int mat = 0; mat < 3; mat++) {
                Bs[ns][mat][wkb + 0][wrow] = __uint_as_float(to_tf32(pwv[mat].x));
                Bs[ns][mat][wkb + 1][wrow] = __uint_as_float(to_tf32(pwv[mat].y));
                Bs[ns][mat][wkb + 2][wrow] = __uint_as_float(to_tf32(pwv[mat].z));
                Bs[ns][mat][wkb + 3][wrow] = __uint_as_float(to_tf32(pwv[mat].w));
            }
        }
        __syncthreads();
    }

    // epilogue: p = silu(P); qv = silu(Q)*silu(V) stored tf32-rounded
#pragma unroll
    for (int mt = 0; mt < 2; mt++) {
#pragma unroll
        for (int half = 0; half < 2; half++) {
            int m = m0 + wm + mt * 16 + quad + half * 8;
#pragma unroll
            for (int nt = 0; nt < 2; nt++) {
                int n = n0 + wn + nt * 8 + tid4 * 2;
                float cp0 = c[0][mt][nt][half * 2 + 0] + pb[n];
                float cp1 = c[0][mt][nt][half * 2 + 1] + pb[n + 1];
                float cq0 = c[1][mt][nt][half * 2 + 0] + qb[n];
                float cq1 = c[1][mt][nt][half * 2 + 1] + qb[n + 1];
                float cv0 = c[2][mt][nt][half * 2 + 0] + vb[n];
                float cv1 = c[2][mt][nt][half * 2 + 1] + vb[n + 1];
                float2 pv = make_float2(silu_f(cp0), silu_f(cp1));
                float qv0 = silu_f(cq0) * silu_f(cv0);
                float qv1 = silu_f(cq1) * silu_f(cv1);
                float2 qv = make_float2(__uint_as_float(to_tf32(qv0)),
                                        __uint_as_float(to_tf32(qv1)));
                *(float2*)&g_p[m * D1 + n] = pv;
                *(float2*)&g_qv[m * D1 + n] = qv;
            }
        }
    }
}

// ---------------- kernel C: axial Toeplitz + gate (TF32 mma, merged axes per warp) ----------------
// Block = (b, 8-channel group), 512 threads = 16 warps.
// Warp w: channel d = w&7, row-half = w>>3. Both o1 and o2 accumulate into the same
// C fragments; res written into the (dead) X plane area. Only padding is zeroed
// (rows 56..63 full width, cols 56..63 for rows 0..55 — disjoint from data loads).
#define XPL   4608    // plane: 64 rows * 72
#define XPIT  72
#define RPIT  60      // res pitch within reused X plane
#define XOFF  0
#define A1OFF (8 * XPL)            // 36864
#define A2OFF (A1OFF + 8 * 128)    // 37888
#define SMEMC_FLOATS (A2OFF + 8 * 128)   // 38912 floats = 155648 B

__global__ __launch_bounds__(512, 1) void toeplitz_kernel() {
    extern __shared__ float sm[];

    int dg = blockIdx.x;                    // 0..71
    int b  = blockIdx.y;                    // 0..7
    int dbase = dg * 8;
    int tid = threadIdx.x;

    // zero ONLY the padding of each plane: 1024 elems per plane (576 row-pad + 448 col-pad)
    for (int idx = tid; idx < 8 * 1024; idx += 512) {
        int plane = idx >> 10;
        int r = idx & 1023;
        int row, col;
        if (r < 576) { row = 56 + r / XPIT; col = r % XPIT; }
        else         { int rr = r - 576; row = rr >> 3; col = 56 + (rr & 7); }
        sm[XOFF + plane * XPL + row * XPIT + col] = 0.0f;
    }
    // load qv slab into per-channel planes (values already tf32-rounded)
    for (int idx = tid; idx < HW * 2; idx += 512) {
        int pos = idx >> 1;
        int q = (idx & 1) * 4;
        float4 v = *(const float4*)&g_qv[(size_t)(b * HW + pos) * D1 + dbase + q];
        int i = pos / N, j = pos % N;
        int base = i * XPIT + j;
        sm[XOFF + (q + 0) * XPL + base] = v.x;
        sm[XOFF + (q + 1) * XPL + base] = v.y;
        sm[XOFF + (q + 2) * XPL + base] = v.z;
        sm[XOFF + (q + 3) * XPL + base] = v.w;
    }
    // coefficient vectors: ap[d][k] = a[(k-63) mod 112][dbase+d] (tf32-rounded)
    for (int idx = tid; idx < 8 * 128; idx += 512) {
        int dd = idx >> 7, k = idx & 127;
        int src = (k + 49) % TWO_N;
        sm[A1OFF + idx] = g_a[src * D1 + dbase + dd];
        sm[A2OFF + idx] = g_a[TWO_N * D1 + src * D1 + dbase + dd];
    }
    __syncthreads();

    int w = tid >> 5, lane = tid & 31;
    int d = w & 7, half = w >> 3;
    int g = lane >> 2, t4 = lane & 3;
    float* X  = sm + XOFF + d * XPL;
    float* A1 = sm + A1OFF + d * 128;
    float* A2 = sm + A2OFF + d * 128;
    int M0 = half * 32;

    float C[2][7][4];
#pragma unroll
    for (int mt = 0; mt < 2; mt++)
#pragma unroll
        for (int nt = 0; nt < 7; nt++)
#pragma unroll
            for (int r = 0; r < 4; r++) C[mt][nt][r] = 0.0f;

    // ---- o1[i][j] = sum_jp X[i][jp] * a1[(j-jp) mod 112] ----
    for (int kt = 0; kt < 8; kt++) {
        int k0 = kt * 8;
        uint32_t a[2][4];
#pragma unroll
        for (int mt = 0; mt < 2; mt++) {
            int r0 = M0 + mt * 16;
            a[mt][0] = __float_as_uint(X[(r0 + g) * XPIT + k0 + t4]);
            a[mt][1] = __float_as_uint(X[(r0 + g + 8) * XPIT + k0 + t4]);
            a[mt][2] = __float_as_uint(X[(r0 + g) * XPIT + k0 + t4 + 4]);
            a[mt][3] = __float_as_uint(X[(r0 + g + 8) * XPIT + k0 + t4 + 4]);
        }
#pragma unroll
        for (int nt = 0; nt < 7; nt++) {
            int idx0 = nt * 8 + g - k0 - t4 + 63;
            uint32_t bb[2];
            bb[0] = __float_as_uint(A1[idx0]);
            bb[1] = __float_as_uint(A1[idx0 - 4]);
#pragma unroll
            for (int mt = 0; mt < 2; mt++)
                mma_tf32(C[mt][nt], a[mt], bb);
        }
    }
    // ---- o2[i][j] = sum_ip a2[(i-ip) mod 112] * X[ip][j] (same C accumulators) ----
    for (int kt = 0; kt < 8; kt++) {
        int k0 = kt * 8;
        uint32_t a[2][4];
#pragma unroll
        for (int mt = 0; mt < 2; mt++) {
            int r0 = M0 + mt * 16;
            a[mt][0] = __float_as_uint(A2[r0 + g - k0 - t4 + 63]);
            a[mt][1] = __float_as_uint(A2[r0 + g + 8 - k0 - t4 + 63]);
            a[mt][2] = __float_as_uint(A2[r0 + g - k0 - t4 - 4 + 63]);
            a[mt][3] = __float_as_uint(A2[r0 + g + 8 - k0 - t4 - 4 + 63]);
        }
#pragma unroll
        for (int nt = 0; nt < 7; nt++) {
            uint32_t bb[2];
            bb[0] = __float_as_uint(X[(k0 + t4) * XPIT + nt * 8 + g]);
            bb[1] = __float_as_uint(X[(k0 + t4 + 4) * XPIT + nt * 8 + g]);
#pragma unroll
            for (int mt = 0; mt < 2; mt++)
                mma_tf32(C[mt][nt], a[mt], bb);
        }
    }
    __syncthreads();    // all X reads done -> X planes reusable as res buffer

    // write res (o1+o2) into reused X plane area
    {
        float* R = sm + XOFF + d * XPL;
#pragma unroll
        for (int mt = 0; mt < 2; mt++) {
            int ia = M0 + mt * 16 + g;
            int ib = ia + 8;
#pragma unroll
            for (int nt = 0; nt < 7; nt++) {
                int j = nt * 8 + 2 * t4;
                if (ia < 56) {
                    R[ia * RPIT + j]     = C[mt][nt][0];
                    R[ia * RPIT + j + 1] = C[mt][nt][1];
                }
                if (ib < 56) {
                    R[ib * RPIT + j]     = C[mt][nt][2];
                    R[ib * RPIT + j + 1] = C[mt][nt][3];
                }
            }
        }
    }
    __syncthreads();

    // gated coalesced store: g_t = g_p * (o1 + o2), all 56 rows
    for (int idx = tid; idx < HW * 2; idx += 512) {
        int pos = idx >> 1;
        int q = (idx & 1) * 4;
        int ir = pos / N, j = pos % N;
        size_t gidx = (size_t)(b * HW + pos) * D1 + dbase + q;
        float4 pv = *(const float4*)&g_p[gidx];
        int base = ir * RPIT + j;
        float4 o;
        o.x = pv.x * sm[XOFF + (q + 0) * XPL + base];
        o.y = pv.y * sm[XOFF + (q + 1) * XPL + base];
        o.z = pv.z * sm[XOFF + (q + 2) * XPL + base];
        o.w = pv.w * sm[XOFF + (q + 3) * XPL + base];
        *(float4*)&g_t[gidx] = o;
    }
}

// ---------------- kernel D: output GEMM (TF32 mma, 2-stage pipeline, 3 blocks/SM) ----------------
#define OBPITCH 72
#define OUT_SMEM ((2 * 32 * APITCH + 2 * 32 * OBPITCH) * 4)   // 53248 B
__global__ __launch_bounds__(256, 3) void out_gemm_kernel(
    const float* __restrict__ ow, const float* __restrict__ ob,
    float* __restrict__ out) {
    extern __shared__ float smem[];
    float (*As)[32][APITCH]  = (float (*)[32][APITCH])smem;
    float (*Bs)[32][OBPITCH] = (float (*)[32][OBPITCH])(smem + 2 * 32 * APITCH);

    int tid = threadIdx.x;
    int warp = tid >> 5, lane = tid & 31;
    int wm = (warp >> 1) * 32;
    int wn = (warp & 1) * 32;
    int quad = lane >> 2, tid4 = lane & 3;
    int m0 = blockIdx.y * 128, n0 = blockIdx.x * 64;

    int lrow = tid >> 1;
    int lcb  = (tid & 1) * 16;
    int wrow = tid >> 2;
    int wkb  = (tid & 3) * 8;

    float c[2][4][4];
#pragma unroll
    for (int i = 0; i < 2; i++)
#pragma unroll
        for (int j = 0; j < 4; j++)
#pragma unroll
            for (int r = 0; r < 4; r++) c[i][j][r] = 0.0f;

    float4 pa[4];
    float4 pb2[2];

#pragma unroll
    for (int v = 0; v < 4; v++)
        pa[v] = *(const float4*)&g_t[(size_t)(m0 + lrow) * D1 + lcb + v * 4];
    pb2[0] = *(const float4*)&ow[(n0 + wrow) * D1 + wkb];
    pb2[1] = *(const float4*)&ow[(n0 + wrow) * D1 + wkb + 4];
    {
#pragma unroll
        for (int v = 0; v < 4; v++) {
            As[0][lcb + v * 4 + 0][lrow] = __uint_as_float(to_tf32(pa[v].x));
            As[0][lcb + v * 4 + 1][lrow] = __uint_as_float(to_tf32(pa[v].y));
            As[0][lcb + v * 4 + 2][lrow] = __uint_as_float(to_tf32(pa[v].z));
            As[0][lcb + v * 4 + 3][lrow] = __uint_as_float(to_tf32(pa[v].w));
        }
        Bs[0][wkb + 0][wrow] = __uint_as_float(to_tf32(pb2[0].x));
        Bs[0][wkb + 1][wrow] = __uint_as_float(to_tf32(pb2[0].y));
        Bs[0][wkb + 2][wrow] = __uint_as_float(to_tf32(pb2[0].z));
        Bs[0][wkb + 3][wrow] = __uint_as_float(to_tf32(pb2[0].w));
        Bs[0][wkb + 4][wrow] = __uint_as_float(to_tf32(pb2[1].x));
        Bs[0][wkb + 5][wrow] = __uint_as_float(to_tf32(pb2[1].y));
        Bs[0][wkb + 6][wrow] = __uint_as_float(to_tf32(pb2[1].z));
        Bs[0][wkb + 7][wrow] = __uint_as_float(to_tf32(pb2[1].w));
    }
    __syncthreads();

    int s = 0;
    for (int kb = 0; kb < D1; kb += 32, s ^= 1) {
        bool hasNext = (kb + 32) < D1;
        if (hasNext) {
            int kn = kb + 32;
#pragma unroll
            for (int v = 0; v < 4; v++)
                pa[v] = *(const float4*)&g_t[(size_t)(m0 + lrow) * D1 + kn + lcb + v * 4];
            pb2[0] = *(const float4*)&ow[(n0 + wrow) * D1 + kn + wkb];
            pb2[1] = *(const float4*)&ow[(n0 + wrow) * D1 + kn + wkb + 4];
        }

#pragma unroll
        for (int k8 = 0; k8 < 32; k8 += 8) {
            uint32_t a[2][4];
#pragma unroll
            for (int mt = 0; mt < 2; mt++) {
                int mb = wm + mt * 16;
                a[mt][0] = __float_as_uint(As[s][k8 + tid4][mb + quad]);
                a[mt][1] = __float_as_uint(As[s][k8 + tid4][mb + quad + 8]);
                a[mt][2] = __float_as_uint(As[s][k8 + tid4 + 4][mb + quad]);
                a[mt][3] = __float_as_uint(As[s][k8 + tid4 + 4][mb + quad + 8]);
            }
#pragma unroll
            for (int nt = 0; nt < 4; nt++) {
                uint32_t b[2];
                int nb = wn + nt * 8 + quad;
                b[0] = __float_as_uint(Bs[s][k8 + tid4][nb]);
                b[1] = __float_as_uint(Bs[s][k8 + tid4 + 4][nb]);
#pragma unroll
                for (int mt = 0; mt < 2; mt++)
                    mma_tf32(c[mt][nt], a[mt], b);
            }
        }

        if (hasNext) {
            int ns = s ^ 1;
#pragma unroll
            for (int v = 0; v < 4; v++) {
                As[ns][lcb + v * 4 + 0][lrow] = __uint_as_float(to_tf32(pa[v].x));
                As[ns][lcb + v * 4 + 1][lrow] = __uint_as_float(to_tf32(pa[v].y));
                As[ns][lcb + v * 4 + 2][lrow] = __uint_as_float(to_tf32(pa[v].z));
                As[ns][lcb + v * 4 + 3][lrow] = __uint_as_float(to_tf32(pa[v].w));
            }
            Bs[ns][wkb + 0][wrow] = __uint_as_float(to_tf32(pb2[0].x));
            Bs[ns][wkb + 1][wrow] = __uint_as_float(to_tf32(pb2[0].y));
            Bs[ns][wkb + 2][wrow] = __uint_as_float(to_tf32(pb2[0].z));
            Bs[ns][wkb + 3][wrow] = __uint_as_float(to_tf32(pb2[0].w));
            Bs[ns][wkb + 4][wrow] = __uint_as_float(to_tf32(pb2[1].x));
            Bs[ns][wkb + 5][wrow] = __uint_as_float(to_tf32(pb2[1].y));
            Bs[ns][wkb + 6][wrow] = __uint_as_float(to_tf32(pb2[1].z));
            Bs[ns][wkb + 7][wrow] = __uint_as_float(to_tf32(pb2[1].w));
        }
        __syncthreads();
    }

#pragma unroll
    for (int mt = 0; mt < 2; mt++) {
#pragma unroll
        for (int half = 0; half < 2; half++) {
            int m = m0 + wm + mt * 16 + quad + half * 8;
#pragma unroll
            for (int nt = 0; nt < 4; nt++) {
                int n = n0 + wn + nt * 8 + tid4 * 2;
                float2 o = make_float2(c[mt][nt][half * 2 + 0] + ob[n],
                                       c[mt][nt][half * 2 + 1] + ob[n + 1]);
                *(float2*)&out[m * EMBED + n] = o;
            }
        }
    }
}

// ---------------- launch ----------------
extern "C" void kernel_launch(void* const* d_in, const int* in_sizes, int n_in,
                              void* d_out, int out_size) {
    const float* x    = (const float*)d_in[0];
    const float* p_w  = (const float*)d_in[1];
    const float* p_b  = (const float*)d_in[2];
    const float* q_w  = (const float*)d_in[3];
    const float* q_b  = (const float*)d_in[4];
    const float* v_w  = (const float*)d_in[5];
    const float* v_b  = (const float*)d_in[6];
    const float* o_w  = (const float*)d_in[7];
    const float* o_b  = (const float*)d_in[8];
    const float* slope = (const float*)d_in[9];
    const float* t1_w0 = (const float*)d_in[10];
    const float* t1_b0 = (const float*)d_in[11];
    const float* t1_ws = (const float*)d_in[12];
    const float* t1_bs = (const float*)d_in[13];
    const float* t1_wo = (const float*)d_in[14];
    const float* t1_bo = (const float*)d_in[15];
    const float* t2_w0 = (const float*)d_in[16];
    const float* t2_b0 = (const float*)d_in[17];
    const float* t2_ws = (const float*)d_in[18];
    const float* t2_bs = (const float*)d_in[19];
    const float* t2_wo = (const float*)d_in[20];
    const float* t2_bo = (const float*)d_in[21];
    float* out = (float*)d_out;

    static const int smemC = SMEMC_FLOATS * (int)sizeof(float);   // 155648 B
    cudaFuncSetAttribute(toeplitz_kernel, cudaFuncAttributeMaxDynamicSharedMemorySize, smemC);
    cudaFuncSetAttribute(pqv_kernel, cudaFuncAttributeMaxDynamicSharedMemorySize, PQV_SMEM);
    cudaFuncSetAttribute(out_gemm_kernel, cudaFuncAttributeMaxDynamicSharedMemorySize, OUT_SMEM);

    rpe_kernel<<<2 * TWO_N, 128>>>(t1_w0, t1_b0, t1_ws, t1_bs, t1_wo, t1_bo,
                                   t2_w0, t2_b0, t2_ws, t2_bs, t2_wo, t2_bo, slope);
    pqv_kernel<<<dim3(D1 / 32, TOK / 128), 256, PQV_SMEM>>>(x, p_w, p_b, q_w, q_b, v_w, v_b);
    toeplitz_kernel<<<dim3(D1 / 8, B), 512, smemC>>>();
    out_gemm_kernel<<<dim3(EMBED / 64, TOK / 128), 256, OUT_SMEM>>>(o_w, o_b, out);
}

// round 16
// speedup vs baseline: 1.9001x; 1.0044x over previous
#include <cuda_runtime.h>
#include <cuda_bf16.h>
#include <math.h>
#include <stdint.h>

#define B 8
#define N 56
#define HW 3136           // 56*56
#define TOK 25088         // 8*56*56
#define EMBED 192
#define D1 576
#define TWO_N 112
#define RPE_H 32

// ---------------- device scratch ----------------
__device__ float g_p[TOK * D1];
__device__ float g_qv[TOK * D1];    // tf32-rounded values (toeplitz-only consumer)
__device__ float g_t[TOK * D1];
__device__ float g_a[2 * TWO_N * D1];   // tf32-rounded (toeplitz-only consumer)

__device__ __forceinline__ float silu_f(float x) {
    return __fdividef(x, 1.0f + __expf(-x));
}

__device__ __forceinline__ uint32_t to_tf32(float x) {
    uint32_t r;
    asm("cvt.rna.tf32.f32 %0, %1;" : "=r"(r) : "f"(x));
    return r;
}

__device__ __forceinline__ void mma_tf32(float c[4], const uint32_t a[4], const uint32_t b[2]) {
    asm volatile(
        "mma.sync.aligned.m16n8k8.row.col.f32.tf32.tf32.f32 "
        "{%0,%1,%2,%3}, {%4,%5,%6,%7}, {%8,%9}, {%0,%1,%2,%3};"
        : "+f"(c[0]), "+f"(c[1]), "+f"(c[2]), "+f"(c[3])
        : "r"(a[0]), "r"(a[1]), "r"(a[2]), "r"(a[3]), "r"(b[0]), "r"(b[1]));
}

// ---------------- kernel A: RPE (hidden MLP + output layer + decay, merged) ----------------
__global__ void rpe_kernel(const float* __restrict__ w0a, const float* __restrict__ b0a,
                           const float* __restrict__ wsa, const float* __restrict__ bsa,
                           const float* __restrict__ wo1, const float* __restrict__ bo1,
                           const float* __restrict__ w0b, const float* __restrict__ b0b,
                           const float* __restrict__ wsb, const float* __restrict__ bsb,
                           const float* __restrict__ wo2, const float* __restrict__ bo2,
                           const float* __restrict__ slope) {
    int bx = blockIdx.x;            // 0..223
    int tno = bx / TWO_N;
    int row = bx % TWO_N;
    const float* W0 = tno ? w0b : w0a;
    const float* B0 = tno ? b0b : b0a;
    const float* WS = tno ? wsb : wsa;
    const float* BS = tno ? bsb : bsa;
    const float* WO = tno ? wo2 : wo1;
    const float* BO = tno ? bo2 : bo1;

    __shared__ float hs[RPE_H];
    int lane = threadIdx.x;

    if (lane < RPE_H) {
        float tv;
        if (row == 0 || row == 56) tv = 0.0f;
        else if (row < 56) tv = (float)row;
        else tv = -(float)(row - 56);

        float h = tv * W0[lane] + B0[lane];
        hs[lane] = h;
        __syncwarp();
        for (int L = 0; L < 3; L++) {
            float s = BS[L * RPE_H + lane];
#pragma unroll
            for (int k = 0; k < RPE_H; k++)
                s += fmaxf(hs[k], 0.0f) * WS[L * RPE_H * RPE_H + lane * RPE_H + k];
            __syncwarp();
            hs[lane] = s;
            __syncwarp();
        }
        hs[lane] = fmaxf(hs[lane], 0.0f);
    }
    __syncthreads();

    int e;
    if (row == 0 || row == 56) e = 0;
    else if (row < 56) e = row;
    else e = TWO_N - row;

    for (int d = threadIdx.x; d < D1; d += blockDim.x) {
        float s = BO[d];
#pragma unroll
        for (int k = 0; k < RPE_H; k++) s += hs[k] * WO[d * RPE_H + k];
        float sl = slope[d];
        sl = fminf(fmaxf(sl, 0.0f), 1.0f);
        sl = 0.95f + 0.05f * sl;
        float dec = (e == 0) ? 1.0f : __powf(sl, (float)e);
        g_a[(tno * TWO_N + row) * D1 + d] = __uint_as_float(to_tf32(s * dec));
    }
}

// ---------------- kernel B: fused p / q*v GEMMs (TF32 mma, 2-stage pipeline, BN=32) ----------------
#define APITCH 136   // ≡ 8 mod 32 -> conflict-free frag loads
#define BPITCH 40    // ≡ 8 mod 32
#define PQV_SMEM ((2 * 32 * APITCH + 2 * 3 * 32 * BPITCH) * 4)   // 65536 B

__global__ __launch_bounds__(256, 2) void pqv_kernel(
    const float* __restrict__ x,
    const float* __restrict__ pw, const float* __restrict__ pb,
    const float* __restrict__ qw, const float* __restrict__ qb,
    const float* __restrict__ vw, const float* __restrict__ vb) {
    extern __shared__ float smem[];
    float (*As)[32][APITCH]    = (float (*)[32][APITCH])smem;
    float (*Bs)[3][32][BPITCH] = (float (*)[3][32][BPITCH])(smem + 2 * 32 * APITCH);

    int tid = threadIdx.x;
    int warp = tid >> 5, lane = tid & 31;
    int wm = (warp >> 1) * 32;
    int wn = (warp & 1) * 16;
    int quad = lane >> 2, tid4 = lane & 3;
    int m0 = blockIdx.y * 128, n0 = blockIdx.x * 32;

    int lrow = tid >> 1;
    int lcb  = (tid & 1) * 16;
    int wrow = tid >> 3;
    int wkb  = (tid & 7) * 4;

    const float* wmats[3] = {pw, qw, vw};

    float c[3][2][2][4];
#pragma unroll
    for (int mt2 = 0; mt2 < 3; mt2++)
#pragma unroll
        for (int i = 0; i < 2; i++)
#pragma unroll
            for (int j = 0; j < 2; j++)
#pragma unroll
                for (int r = 0; r < 4; r++) c[mt2][i][j][r] = 0.0f;

    float4 pa[4];
    float4 pwv[3];

#pragma unroll
    for (int v = 0; v < 4; v++)
        pa[v] = *(const float4*)&x[(m0 + lrow) * EMBED + lcb + v * 4];
#pragma unroll
    for (int mat = 0; mat < 3; mat++)
        pwv[mat] = *(const float4*)&wmats[mat][(n0 + wrow) * EMBED + wkb];
    {
#pragma unroll
        for (int v = 0; v < 4; v++) {
            As[0][lcb + v * 4 + 0][lrow] = __uint_as_float(to_tf32(pa[v].x));
            As[0][lcb + v * 4 + 1][lrow] = __uint_as_float(to_tf32(pa[v].y));
            As[0][lcb + v * 4 + 2][lrow] = __uint_as_float(to_tf32(pa[v].z));
            As[0][lcb + v * 4 + 3][lrow] = __uint_as_float(to_tf32(pa[v].w));
        }
#pragma unroll
        for (int mat = 0; mat < 3; mat++) {
            Bs[0][mat][wkb + 0][wrow] = __uint_as_float(to_tf32(pwv[mat].x));
            Bs[0][mat][wkb + 1][wrow] = __uint_as_float(to_tf32(pwv[mat].y));
            Bs[0][mat][wkb + 2][wrow] = __uint_as_float(to_tf32(pwv[mat].z));
            Bs[0][mat][wkb + 3][wrow] = __uint_as_float(to_tf32(pwv[mat].w));
        }
    }
    __syncthreads();

    int s = 0;
    for (int kb = 0; kb < EMBED; kb += 32, s ^= 1) {
        bool hasNext = (kb + 32) < EMBED;
        if (hasNext) {
            int kn = kb + 32;
#pragma unroll
            for (int v = 0; v < 4; v++)
                pa[v] = *(const float4*)&x[(m0 + lrow) * EMBED + kn + lcb + v * 4];
#pragma unroll
            for (int mat = 0; mat < 3; mat++)
                pwv[mat] = *(const float4*)&wmats[mat][(n0 + wrow) * EMBED + kn + wkb];
        }

#pragma unroll
        for (int k8 = 0; k8 < 32; k8 += 8) {
            uint32_t a[2][4];
#pragma unroll
            for (int mt = 0; mt < 2; mt++) {
                int mb = wm + mt * 16;
                a[mt][0] = __float_as_uint(As[s][k8 + tid4][mb + quad]);
                a[mt][1] = __float_as_uint(As[s][k8 + tid4][mb + quad + 8]);
                a[mt][2] = __float_as_uint(As[s][k8 + tid4 + 4][mb + quad]);
                a[mt][3] = __float_as_uint(As[s][k8 + tid4 + 4][mb + quad + 8]);
            }
#pragma unroll
            for (int mat = 0; mat < 3; mat++) {
#pragma unroll
                for (int nt = 0; nt < 2; nt++) {
                    uint32_t b[2];
                    int nb = wn + nt * 8 + quad;
                    b[0] = __float_as_uint(Bs[s][mat][k8 + tid4][nb]);
                    b[1] = __float_as_uint(Bs[s][mat][k8 + tid4 + 4][nb]);
#pragma unroll
                    for (int mt = 0; mt < 2; mt++)
                        mma_tf32(c[mat][mt][nt], a[mt], b);
                }
            }
        }

        if (hasNext) {
            int ns = s ^ 1;
#pragma unroll
            for (int v = 0; v < 4; v++) {
                As[ns][lcb + v * 4 + 0][lrow] = __uint_as_float(to_tf32(pa[v].x));
                As[ns][lcb + v * 4 + 1][lrow] = __uint_as_float(to_tf32(pa[v].y));
                As[ns][lcb + v * 4 + 2][lrow] = __uint_as_float(to_tf32(pa[v].z));
                As[ns][lcb + v * 4 + 3][lrow] = __uint_as_float(to_tf32(pa[v].w));
            }
#pragma unroll
            for (int mat = 0; mat < 3; mat++) {
                Bs[ns][mat][wkb + 0][wrow] = __uint_as_float(to_tf32(pwv[mat].x));
                Bs[ns][mat][wkb + 1][wrow] = __uint_as_float(to_tf32(pwv[mat].y));
                Bs[ns][mat][wkb + 2][wrow] = __uint_as_float(to_tf32(pwv[mat].z));
                Bs[ns][mat][wkb + 3][wrow] = __uint_as_float(to_tf32(pwv[mat].w));
            }
        }
        __syncthreads();
    }

    // epilogue: p = silu(P); qv = silu(Q)*silu(V) stored tf32-rounded
#pragma unroll
    for (int mt = 0; mt < 2; mt++) {
#pragma unroll
        for (int half = 0; half < 2; half++) {
            int m = m0 + wm + mt * 16 + quad + half * 8;
#pragma unroll
            for (int nt = 0; nt < 2; nt++) {
                int n = n0 + wn + nt * 8 + tid4 * 2;
                float cp0 = c[0][mt][nt][half * 2 + 0] + pb[n];
                float cp1 = c[0][mt][nt][half * 2 + 1] + pb[n + 1];
                float cq0 = c[1][mt][nt][half * 2 + 0] + qb[n];
                float cq1 = c[1][mt][nt][half * 2 + 1] + qb[n + 1];
                float cv0 = c[2][mt][nt][half * 2 + 0] + vb[n];
                float cv1 = c[2][mt][nt][half * 2 + 1] + vb[n + 1];
                float2 pv = make_float2(silu_f(cp0), silu_f(cp1));
                float qv0 = silu_f(cq0) * silu_f(cv0);
                float qv1 = silu_f(cq1) * silu_f(cv1);
                float2 qv = make_float2(__uint_as_float(to_tf32(qv0)),
                                        __uint_as_float(to_tf32(qv1)));
                *(float2*)&g_p[m * D1 + n] = pv;
                *(float2*)&g_qv[m * D1 + n] = qv;
            }
        }
    }
}

// ---------------- kernel C: axial Toeplitz + gate (TF32 mma, 4-ch blocks, no padding) ----------------
// Block = (b, 4-channel group), 256 threads = 8 warps, 2 blocks/SM.
// Warp w: channel d = w&3, row-half = w>>2. Both o1 and o2 accumulate into the same
// C fragments. kt runs 0..6 only: the k=56..63 slab multiplies zero X data (o1 a-frags /
// o2 b-frags) so its contribution is exactly zero — dropped. The only reads beyond
// row/col 55 are o1 a-frags feeding discarded C lanes (rows 56..63), which stay inside
// the smem allocation and cannot pollute valid outputs (mma lanes independent).
#define CH    4
#define XPL   4032    // plane: 56 rows * 72
#define XPIT  72
#define RPIT  60      // res pitch within reused X plane
#define XOFF  0
#define A1OFF (CH * XPL)             // 16128
#define A2OFF (A1OFF + CH * 128)     // 16640
#define SMEMC_FLOATS (A2OFF + CH * 128)   // 17152 floats = 68608 B

__global__ __launch_bounds__(256, 2) void toeplitz_kernel() {
    extern __shared__ float sm[];

    int dg = blockIdx.x;                    // 0..143
    int b  = blockIdx.y;                    // 0..7
    int dbase = dg * CH;
    int tid = threadIdx.x;

    // load qv slab into per-channel planes (values already tf32-rounded)
    for (int pos = tid; pos < HW; pos += 256) {
        float4 v = *(const float4*)&g_qv[(size_t)(b * HW + pos) * D1 + dbase];
        int i = pos / N, j = pos % N;
        int base = i * XPIT + j;
        sm[XOFF + 0 * XPL + base] = v.x;
        sm[XOFF + 1 * XPL + base] = v.y;
        sm[XOFF + 2 * XPL + base] = v.z;
        sm[XOFF + 3 * XPL + base] = v.w;
    }
    // coefficient vectors: ap[d][k] = a[(k-63) mod 112][dbase+d] (tf32-rounded)
    for (int idx = tid; idx < CH * 128; idx += 256) {
        int dd = idx >> 7, k = idx & 127;
        int src = (k + 49) % TWO_N;
        sm[A1OFF + idx] = g_a[src * D1 + dbase + dd];
        sm[A2OFF + idx] = g_a[TWO_N * D1 + src * D1 + dbase + dd];
    }
    __syncthreads();

    int w = tid >> 5, lane = tid & 31;
    int d = w & 3, half = w >> 2;
    int g = lane >> 2, t4 = lane & 3;
    float* X  = sm + XOFF + d * XPL;
    float* A1 = sm + A1OFF + d * 128;
    float* A2 = sm + A2OFF + d * 128;
    int M0 = half * 32;

    float C[2][7][4];
#pragma unroll
    for (int mt = 0; mt < 2; mt++)
#pragma unroll
        for (int nt = 0; nt < 7; nt++)
#pragma unroll
            for (int r = 0; r < 4; r++) C[mt][nt][r] = 0.0f;

    // ---- o1[i][j] = sum_jp X[i][jp] * a1[(j-jp) mod 112], jp = 0..55 ----
    for (int kt = 0; kt < 7; kt++) {
        int k0 = kt * 8;
        uint32_t a[2][4];
#pragma unroll
        for (int mt = 0; mt < 2; mt++) {
            int r0 = M0 + mt * 16;
            a[mt][0] = __float_as_uint(X[(r0 + g) * XPIT + k0 + t4]);
            a[mt][1] = __float_as_uint(X[(r0 + g + 8) * XPIT + k0 + t4]);
            a[mt][2] = __float_as_uint(X[(r0 + g) * XPIT + k0 + t4 + 4]);
            a[mt][3] = __float_as_uint(X[(r0 + g + 8) * XPIT + k0 + t4 + 4]);
        }
#pragma unroll
        for (int nt = 0; nt < 7; nt++) {
            int idx0 = nt * 8 + g - k0 - t4 + 63;
            uint32_t bb[2];
            bb[0] = __float_as_uint(A1[idx0]);
            bb[1] = __float_as_uint(A1[idx0 - 4]);
#pragma unroll
            for (int mt = 0; mt < 2; mt++)
                mma_tf32(C[mt][nt], a[mt], bb);
        }
    }
    // ---- o2[i][j] = sum_ip a2[(i-ip) mod 112] * X[ip][j], ip = 0..55 ----
    for (int kt = 0; kt < 7; kt++) {
        int k0 = kt * 8;
        uint32_t a[2][4];
#pragma unroll
        for (int mt = 0; mt < 2; mt++) {
            int r0 = M0 + mt * 16;
            a[mt][0] = __float_as_uint(A2[r0 + g - k0 - t4 + 63]);
            a[mt][1] = __float_as_uint(A2[r0 + g + 8 - k0 - t4 + 63]);
            a[mt][2] = __float_as_uint(A2[r0 + g - k0 - t4 - 4 + 63]);
            a[mt][3] = __float_as_uint(A2[r0 + g + 8 - k0 - t4 - 4 + 63]);
        }
#pragma unroll
        for (int nt = 0; nt < 7; nt++) {
            uint32_t bb[2];
            bb[0] = __float_as_uint(X[(k0 + t4) * XPIT + nt * 8 + g]);
            bb[1] = __float_as_uint(X[(k0 + t4 + 4) * XPIT + nt * 8 + g]);
#pragma unroll
            for (int mt = 0; mt < 2; mt++)
                mma_tf32(C[mt][nt], a[mt], bb);
        }
    }
    __syncthreads();    // all X reads done -> X planes reusable as res buffer

    // write res (o1+o2) into reused X plane area
    {
        float* R = sm + XOFF + d * XPL;
#pragma unroll
        for (int mt = 0; mt < 2; mt++) {
            int ia = M0 + mt * 16 + g;
            int ib = ia + 8;
#pragma unroll
            for (int nt = 0; nt < 7; nt++) {
                int j = nt * 8 + 2 * t4;
                if (ia < 56) {
                    R[ia * RPIT + j]     = C[mt][nt][0];
                    R[ia * RPIT + j + 1] = C[mt][nt][1];
                }
                if (ib < 56) {
                    R[ib * RPIT + j]     = C[mt][nt][2];
                    R[ib * RPIT + j + 1] = C[mt][nt][3];
                }
            }
        }
    }
    __syncthreads();

    // gated coalesced store: g_t = g_p * (o1 + o2)
    for (int pos = tid; pos < HW; pos += 256) {
        int ir = pos / N, j = pos % N;
        size_t gidx = (size_t)(b * HW + pos) * D1 + dbase;
        float4 pv = *(const float4*)&g_p[gidx];
        int base = ir * RPIT + j;
        float4 o;
        o.x = pv.x * sm[XOFF + 0 * XPL + base];
        o.y = pv.y * sm[XOFF + 1 * XPL + base];
        o.z = pv.z * sm[XOFF + 2 * XPL + base];
        o.w = pv.w * sm[XOFF + 3 * XPL + base];
        *(float4*)&g_t[gidx] = o;
    }
}

// ---------------- kernel D: output GEMM (TF32 mma, 2-stage pipeline, 3 blocks/SM) ----------------
#define OBPITCH 72
#define OUT_SMEM ((2 * 32 * APITCH + 2 * 32 * OBPITCH) * 4)   // 53248 B
__global__ __launch_bounds__(256, 3) void out_gemm_kernel(
    const float* __restrict__ ow, const float* __restrict__ ob,
    float* __restrict__ out) {
    extern __shared__ float smem[];
    float (*As)[32][APITCH]  = (float (*)[32][APITCH])smem;
    float (*Bs)[32][OBPITCH] = (float (*)[32][OBPITCH])(smem + 2 * 32 * APITCH);

    int tid = threadIdx.x;
    int warp = tid >> 5, lane = tid & 31;
    int wm = (warp >> 1) * 32;
    int wn = (warp & 1) * 32;
    int quad = lane >> 2, tid4 = lane & 3;
    int m0 = blockIdx.y * 128, n0 = blockIdx.x * 64;

    int lrow = tid >> 1;
    int lcb  = (tid & 1) * 16;
    int wrow = tid >> 2;
    int wkb  = (tid & 3) * 8;

    float c[2][4][4];
#pragma unroll
    for (int i = 0; i < 2; i++)
#pragma unroll
        for (int j = 0; j < 4; j++)
#pragma unroll
            for (int r = 0; r < 4; r++) c[i][j][r] = 0.0f;

    float4 pa[4];
    float4 pb2[2];

#pragma unroll
    for (int v = 0; v < 4; v++)
        pa[v] = *(const float4*)&g_t[(size_t)(m0 + lrow) * D1 + lcb + v * 4];
    pb2[0] = *(const float4*)&ow[(n0 + wrow) * D1 + wkb];
    pb2[1] = *(const float4*)&ow[(n0 + wrow) * D1 + wkb + 4];
    {
#pragma unroll
        for (int v = 0; v < 4; v++) {
            As[0][lcb + v * 4 + 0][lrow] = __uint_as_float(to_tf32(pa[v].x));
            As[0][lcb + v * 4 + 1][lrow] = __uint_as_float(to_tf32(pa[v].y));
            As[0][lcb + v * 4 + 2][lrow] = __uint_as_float(to_tf32(pa[v].z));
            As[0][lcb + v * 4 + 3][lrow] = __uint_as_float(to_tf32(pa[v].w));
        }
        Bs[0][wkb + 0][wrow] = __uint_as_float(to_tf32(pb2[0].x));
        Bs[0][wkb + 1][wrow] = __uint_as_float(to_tf32(pb2[0].y));
        Bs[0][wkb + 2][wrow] = __uint_as_float(to_tf32(pb2[0].z));
        Bs[0][wkb + 3][wrow] = __uint_as_float(to_tf32(pb2[0].w));
        Bs[0][wkb + 4][wrow] = __uint_as_float(to_tf32(pb2[1].x));
        Bs[0][wkb + 5][wrow] = __uint_as_float(to_tf32(pb2[1].y));
        Bs[0][wkb + 6][wrow] = __uint_as_float(to_tf32(pb2[1].z));
        Bs[0][wkb + 7][wrow] = __uint_as_float(to_tf32(pb2[1].w));
    }
    __syncthreads();

    int s = 0;
    for (int kb = 0; kb < D1; kb += 32, s ^= 1) {
        bool hasNext = (kb + 32) < D1;
        if (hasNext) {
            int kn = kb + 32;
#pragma unroll
            for (int v = 0; v < 4; v++)
                pa[v] = *(const float4*)&g_t[(size_t)(m0 + lrow) * D1 + kn + lcb + v * 4];
            pb2[0] = *(const float4*)&ow[(n0 + wrow) * D1 + kn + wkb];
            pb2[1] = *(const float4*)&ow[(n0 + wrow) * D1 + kn + wkb + 4];
        }

#pragma unroll
        for (int k8 = 0; k8 < 32; k8 += 8) {
            uint32_t a[2][4];
#pragma unroll
            for (int mt = 0; mt < 2; mt++) {
                int mb = wm + mt * 16;
                a[mt][0] = __float_as_uint(As[s][k8 + tid4][mb + quad]);
                a[mt][1] = __float_as_uint(As[s][k8 + tid4][mb + quad + 8]);
                a[mt][2] = __float_as_uint(As[s][k8 + tid4 + 4][mb + quad]);
                a[mt][3] = __float_as_uint(As[s][k8 + tid4 + 4][mb + quad + 8]);
            }
#pragma unroll
            for (int nt = 0; nt < 4; nt++) {
                uint32_t b[2];
                int nb = wn + nt * 8 + quad;
                b[0] = __float_as_uint(Bs[s][k8 + tid4][nb]);
                b[1] = __float_as_uint(Bs[s][k8 + tid4 + 4][nb]);
#pragma unroll
                for (int mt = 0; mt < 2; mt++)
                    mma_tf32(c[mt][nt], a[mt], b);
            }
        }

        if (hasNext) {
            int ns = s ^ 1;
#pragma unroll
            for (int v = 0; v < 4; v++) {
                As[ns][lcb + v * 4 + 0][lrow] = __uint_as_float(to_tf32(pa[v].x));
                As[ns][lcb + v * 4 + 1][lrow] = __uint_as_float(to_tf32(pa[v].y));
                As[ns][lcb + v * 4 + 2][lrow] = __uint_as_float(to_tf32(pa[v].z));
                As[ns][lcb + v * 4 + 3][lrow] = __uint_as_float(to_tf32(pa[v].w));
            }
            Bs[ns][wkb + 0][wrow] = __uint_as_float(to_tf32(pb2[0].x));
            Bs[ns][wkb + 1][wrow] = __uint_as_float(to_tf32(pb2[0].y));
            Bs[ns][wkb + 2][wrow] = __uint_as_float(to_tf32(pb2[0].z));
            Bs[ns][wkb + 3][wrow] = __uint_as_float(to_tf32(pb2[0].w));
            Bs[ns][wkb + 4][wrow] = __uint_as_float(to_tf32(pb2[1].x));
            Bs[ns][wkb + 5][wrow] = __uint_as_float(to_tf32(pb2[1].y));
            Bs[ns][wkb + 6][wrow] = __uint_as_float(to_tf32(pb2[1].z));
            Bs[ns][wkb + 7][wrow] = __uint_as_float(to_tf32(pb2[1].w));
        }
        __syncthreads();
    }

#pragma unroll
    for (int mt = 0; mt < 2; mt++) {
#pragma unroll
        for (int half = 0; half < 2; half++) {
            int m = m0 + wm + mt * 16 + quad + half * 8;
#pragma unroll
            for (int nt = 0; nt < 4; nt++) {
                int n = n0 + wn + nt * 8 + tid4 * 2;
                float2 o = make_float2(c[mt][nt][half * 2 + 0] + ob[n],
                                       c[mt][nt][half * 2 + 1] + ob[n + 1]);
                *(float2*)&out[m * EMBED + n] = o;
            }
        }
    }
}

// ---------------- launch ----------------
extern "C" void kernel_launch(void* const* d_in, const int* in_sizes, int n_in,
                              void* d_out, int out_size) {
    const float* x    = (const float*)d_in[0];
    const float* p_w  = (const float*)d_in[1];
    const float* p_b  = (const float*)d_in[2];
    const float* q_w  = (const float*)d_in[3];
    const float* q_b  = (const float*)d_in[4];
    const float* v_w  = (const float*)d_in[5];
    const float* v_b  = (const float*)d_in[6];
    const float* o_w  = (const float*)d_in[7];
    const float* o_b  = (const float*)d_in[8];
    const float* slope = (const float*)d_in[9];
    const float* t1_w0 = (const float*)d_in[10];
    const float* t1_b0 = (const float*)d_in[11];
    const float* t1_ws = (const float*)d_in[12];
    const float* t1_bs = (const float*)d_in[13];
    const float* t1_wo = (const float*)d_in[14];
    const float* t1_bo = (const float*)d_in[15];
    const float* t2_w0 = (const float*)d_in[16];
    const float* t2_b0 = (const float*)d_in[17];
    const float* t2_ws = (const float*)d_in[18];
    const float* t2_bs = (const float*)d_in[19];
    const float* t2_wo = (const float*)d_in[20];
    const float* t2_bo = (const float*)d_in[21];
    float* out = (float*)d_out;

    static const int smemC = SMEMC_FLOATS * (int)sizeof(float);   // 68608 B
    cudaFuncSetAttribute(toeplitz_kernel, cudaFuncAttributeMaxDynamicSharedMemorySize, smemC);
    cudaFuncSetAttribute(pqv_kernel, cudaFuncAttributeMaxDynamicSharedMemorySize, PQV_SMEM);
    cudaFuncSetAttribute(out_gemm_kernel, cudaFuncAttributeMaxDynamicSharedMemorySize, OUT_SMEM);

    rpe_kernel<<<2 * TWO_N, 128>>>(t1_w0, t1_b0, t1_ws, t1_bs, t1_wo, t1_bo,
                                   t2_w0, t2_b0, t2_ws, t2_bs, t2_wo, t2_bo, slope);
    pqv_kernel<<<dim3(D1 / 32, TOK / 128), 256, PQV_SMEM>>>(x, p_w, p_b, q_w, q_b, v_w, v_b);
    toeplitz_kernel<<<dim3(D1 / CH, B), 256, smemC>>>();
    out_gemm_kernel<<<dim3(EMBED / 64, TOK / 128), 256, OUT_SMEM>>>(o_w, o_b, out);
}

// round 17
// speedup vs baseline: 1.9934x; 1.0491x over previous
#include <cuda_runtime.h>
#include <cuda_bf16.h>
#include <math.h>
#include <stdint.h>

#define B 8
#define N 56
#define HW 3136           // 56*56
#define TOK 25088         // 8*56*56
#define EMBED 192
#define D1 576
#define TWO_N 112
#define RPE_H 32

// ---------------- device scratch ----------------
__device__ float g_p[TOK * D1];
__device__ float g_qv[TOK * D1];    // tf32-rounded values (toeplitz-only consumer)
__device__ float g_t[TOK * D1];
__device__ float g_a[2 * TWO_N * D1];   // tf32-rounded (toeplitz-only consumer)

__device__ __forceinline__ float silu_f(float x) {
    return __fdividef(x, 1.0f + __expf(-x));
}

__device__ __forceinline__ uint32_t to_tf32(float x) {
    uint32_t r;
    asm("cvt.rna.tf32.f32 %0, %1;" : "=r"(r) : "f"(x));
    return r;
}

__device__ __forceinline__ void mma_tf32(float c[4], const uint32_t a[4], const uint32_t b[2]) {
    asm volatile(
        "mma.sync.aligned.m16n8k8.row.col.f32.tf32.tf32.f32 "
        "{%0,%1,%2,%3}, {%4,%5,%6,%7}, {%8,%9}, {%0,%1,%2,%3};"
        : "+f"(c[0]), "+f"(c[1]), "+f"(c[2]), "+f"(c[3])
        : "r"(a[0]), "r"(a[1]), "r"(a[2]), "r"(a[3]), "r"(b[0]), "r"(b[1]));
}

__device__ __forceinline__ void mma_bf16(float c[4], const uint32_t a[4], const uint32_t b[2]) {
    asm volatile(
        "mma.sync.aligned.m16n8k16.row.col.f32.bf16.bf16.f32 "
        "{%0,%1,%2,%3}, {%4,%5,%6,%7}, {%8,%9}, {%0,%1,%2,%3};"
        : "+f"(c[0]), "+f"(c[1]), "+f"(c[2]), "+f"(c[3])
        : "r"(a[0]), "r"(a[1]), "r"(a[2]), "r"(a[3]), "r"(b[0]), "r"(b[1]));
}

// split two floats (even k, odd k) into packed bf16x2 hi and lo words
__device__ __forceinline__ void split_bf16x2(float f0, float f1, uint32_t& hi, uint32_t& lo) {
    __nv_bfloat162 h = __floats2bfloat162_rn(f0, f1);
    float r0 = f0 - __bfloat162float(__low2bfloat16(h));
    float r1 = f1 - __bfloat162float(__high2bfloat16(h));
    __nv_bfloat162 l = __floats2bfloat162_rn(r0, r1);
    hi = *(uint32_t*)&h;
    lo = *(uint32_t*)&l;
}

// ---------------- kernel A: RPE (hidden MLP + output layer + decay, merged) ----------------
__global__ void rpe_kernel(const float* __restrict__ w0a, const float* __restrict__ b0a,
                           const float* __restrict__ wsa, const float* __restrict__ bsa,
                           const float* __restrict__ wo1, const float* __restrict__ bo1,
                           const float* __restrict__ w0b, const float* __restrict__ b0b,
                           const float* __restrict__ wsb, const float* __restrict__ bsb,
                           const float* __restrict__ wo2, const float* __restrict__ bo2,
                           const float* __restrict__ slope) {
    int bx = blockIdx.x;            // 0..223
    int tno = bx / TWO_N;
    int row = bx % TWO_N;
    const float* W0 = tno ? w0b : w0a;
    const float* B0 = tno ? b0b : b0a;
    const float* WS = tno ? wsb : wsa;
    const float* BS = tno ? bsb : bsa;
    const float* WO = tno ? wo2 : wo1;
    const float* BO = tno ? bo2 : bo1;

    __shared__ float hs[RPE_H];
    int lane = threadIdx.x;

    if (lane < RPE_H) {
        float tv;
        if (row == 0 || row == 56) tv = 0.0f;
        else if (row < 56) tv = (float)row;
        else tv = -(float)(row - 56);

        float h = tv * W0[lane] + B0[lane];
        hs[lane] = h;
        __syncwarp();
        for (int L = 0; L < 3; L++) {
            float s = BS[L * RPE_H + lane];
#pragma unroll
            for (int k = 0; k < RPE_H; k++)
                s += fmaxf(hs[k], 0.0f) * WS[L * RPE_H * RPE_H + lane * RPE_H + k];
            __syncwarp();
            hs[lane] = s;
            __syncwarp();
        }
        hs[lane] = fmaxf(hs[lane], 0.0f);
    }
    __syncthreads();

    int e;
    if (row == 0 || row == 56) e = 0;
    else if (row < 56) e = row;
    else e = TWO_N - row;

    for (int d = threadIdx.x; d < D1; d += blockDim.x) {
        float s = BO[d];
#pragma unroll
        for (int k = 0; k < RPE_H; k++) s += hs[k] * WO[d * RPE_H + k];
        float sl = slope[d];
        sl = fminf(fmaxf(sl, 0.0f), 1.0f);
        sl = 0.95f + 0.05f * sl;
        float dec = (e == 0) ? 1.0f : __powf(sl, (float)e);
        g_a[(tno * TWO_N + row) * D1 + d] = __uint_as_float(to_tf32(s * dec));
    }
}

// ---------------- kernel B: fused p / q*v GEMMs (bf16 split 3-term mma, 2-stage pipeline) ----------------
// BM=128, BN=32, BK=32 (=16 k2 words), 256 threads = 8 warps (4m x 2n), warp tile 32x16.
// A and B split into bf16 hi/lo packed 2-per-word; D = AhBh + AlBh + AhBl (err ~2^-16).
// smem: AsH/AsL [2][16][APITCH] words + BsH/BsL [2][3][16][BPITCH] words = 65536 B -> 2 blocks/SM.
#define APITCH 136   // ≡ 8 mod 32 -> conflict-free frag loads
#define BPITCH 40    // ≡ 8 mod 32
#define A_WORDS (2 * 16 * APITCH)          // 4352 per hi/lo
#define B_WORDS (2 * 3 * 16 * BPITCH)      // 3840 per hi/lo
#define PQV_SMEM ((2 * A_WORDS + 2 * B_WORDS) * 4)   // 65536 B

__global__ __launch_bounds__(256, 2) void pqv_kernel(
    const float* __restrict__ x,
    const float* __restrict__ pw, const float* __restrict__ pb,
    const float* __restrict__ qw, const float* __restrict__ qb,
    const float* __restrict__ vw, const float* __restrict__ vb) {
    extern __shared__ uint32_t smw[];
    uint32_t (*AsH)[16][APITCH]    = (uint32_t (*)[16][APITCH])smw;
    uint32_t (*AsL)[16][APITCH]    = (uint32_t (*)[16][APITCH])(smw + A_WORDS);
    uint32_t (*BsH)[3][16][BPITCH] = (uint32_t (*)[3][16][BPITCH])(smw + 2 * A_WORDS);
    uint32_t (*BsL)[3][16][BPITCH] = (uint32_t (*)[3][16][BPITCH])(smw + 2 * A_WORDS + B_WORDS);

    int tid = threadIdx.x;
    int warp = tid >> 5, lane = tid & 31;
    int wm = (warp >> 1) * 32;
    int wn = (warp & 1) * 16;
    int quad = lane >> 2, tid4 = lane & 3;
    int m0 = blockIdx.y * 128, n0 = blockIdx.x * 32;

    int lrow = tid >> 1;                 // A loader: 0..127
    int lcb  = (tid & 1) * 16;           // A float base (16 floats = 8 k2 words)
    int lk2  = lcb >> 1;
    int wrow = tid >> 3;                 // B loader: 0..31
    int wkb  = (tid & 7) * 4;            // 4 floats = 2 k2 words
    int wk2  = wkb >> 1;

    const float* wmats[3] = {pw, qw, vw};

    float c[3][2][2][4];
#pragma unroll
    for (int mt2 = 0; mt2 < 3; mt2++)
#pragma unroll
        for (int i = 0; i < 2; i++)
#pragma unroll
            for (int j = 0; j < 2; j++)
#pragma unroll
                for (int r = 0; r < 4; r++) c[mt2][i][j][r] = 0.0f;

    float4 pa[4];
    float4 pwv[3];

#pragma unroll
    for (int v = 0; v < 4; v++)
        pa[v] = *(const float4*)&x[(m0 + lrow) * EMBED + lcb + v * 4];
#pragma unroll
    for (int mat = 0; mat < 3; mat++)
        pwv[mat] = *(const float4*)&wmats[mat][(n0 + wrow) * EMBED + wkb];
    {
        const float* pf = (const float*)pa;
#pragma unroll
        for (int v = 0; v < 8; v++) {
            uint32_t hi, lo;
            split_bf16x2(pf[2 * v], pf[2 * v + 1], hi, lo);
            AsH[0][lk2 + v][lrow] = hi;
            AsL[0][lk2 + v][lrow] = lo;
        }
#pragma unroll
        for (int mat = 0; mat < 3; mat++) {
            uint32_t h0, l0, h1, l1;
            split_bf16x2(pwv[mat].x, pwv[mat].y, h0, l0);
            split_bf16x2(pwv[mat].z, pwv[mat].w, h1, l1);
            BsH[0][mat][wk2 + 0][wrow] = h0;
            BsL[0][mat][wk2 + 0][wrow] = l0;
            BsH[0][mat][wk2 + 1][wrow] = h1;
            BsL[0][mat][wk2 + 1][wrow] = l1;
        }
    }
    __syncthreads();

    int s = 0;
    for (int kb = 0; kb < EMBED; kb += 32, s ^= 1) {
        bool hasNext = (kb + 32) < EMBED;
        if (hasNext) {
            int kn = kb + 32;
#pragma unroll
            for (int v = 0; v < 4; v++)
                pa[v] = *(const float4*)&x[(m0 + lrow) * EMBED + kn + lcb + v * 4];
#pragma unroll
            for (int mat = 0; mat < 3; mat++)
                pwv[mat] = *(const float4*)&wmats[mat][(n0 + wrow) * EMBED + kn + wkb];
        }

#pragma unroll
        for (int k16 = 0; k16 < 2; k16++) {
            int k2b = k16 * 8;
            uint32_t ah[2][4], al[2][4];
#pragma unroll
            for (int mt = 0; mt < 2; mt++) {
                int mb = wm + mt * 16;
                ah[mt][0] = AsH[s][k2b + tid4][mb + quad];
                ah[mt][1] = AsH[s][k2b + tid4][mb + quad + 8];
                ah[mt][2] = AsH[s][k2b + tid4 + 4][mb + quad];
                ah[mt][3] = AsH[s][k2b + tid4 + 4][mb + quad + 8];
                al[mt][0] = AsL[s][k2b + tid4][mb + quad];
                al[mt][1] = AsL[s][k2b + tid4][mb + quad + 8];
                al[mt][2] = AsL[s][k2b + tid4 + 4][mb + quad];
                al[mt][3] = AsL[s][k2b + tid4 + 4][mb + quad + 8];
            }
#pragma unroll
            for (int mat = 0; mat < 3; mat++) {
#pragma unroll
                for (int nt = 0; nt < 2; nt++) {
                    int nb = wn + nt * 8 + quad;
                    uint32_t bh[2], bl[2];
                    bh[0] = BsH[s][mat][k2b + tid4][nb];
                    bh[1] = BsH[s][mat][k2b + tid4 + 4][nb];
                    bl[0] = BsL[s][mat][k2b + tid4][nb];
                    bl[1] = BsL[s][mat][k2b + tid4 + 4][nb];
#pragma unroll
                    for (int mt = 0; mt < 2; mt++) {
                        mma_bf16(c[mat][mt][nt], ah[mt], bh);
                        mma_bf16(c[mat][mt][nt], al[mt], bh);
                        mma_bf16(c[mat][mt][nt], ah[mt], bl);
                    }
                }
            }
        }

        if (hasNext) {
            int ns = s ^ 1;
            const float* pf = (const float*)pa;
#pragma unroll
            for (int v = 0; v < 8; v++) {
                uint32_t hi, lo;
                split_bf16x2(pf[2 * v], pf[2 * v + 1], hi, lo);
                AsH[ns][lk2 + v][lrow] = hi;
                AsL[ns][lk2 + v][lrow] = lo;
            }
#pragma unroll
            for (int mat = 0; mat < 3; mat++) {
                uint32_t h0, l0, h1, l1;
                split_bf16x2(pwv[mat].x, pwv[mat].y, h0, l0);
                split_bf16x2(pwv[mat].z, pwv[mat].w, h1, l1);
                BsH[ns][mat][wk2 + 0][wrow] = h0;
                BsL[ns][mat][wk2 + 0][wrow] = l0;
                BsH[ns][mat][wk2 + 1][wrow] = h1;
                BsL[ns][mat][wk2 + 1][wrow] = l1;
            }
        }
        __syncthreads();
    }

    // epilogue: p = silu(P); qv = silu(Q)*silu(V) stored tf32-rounded (for toeplitz)
#pragma unroll
    for (int mt = 0; mt < 2; mt++) {
#pragma unroll
        for (int half = 0; half < 2; half++) {
            int m = m0 + wm + mt * 16 + quad + half * 8;
#pragma unroll
            for (int nt = 0; nt < 2; nt++) {
                int n = n0 + wn + nt * 8 + tid4 * 2;
                float cp0 = c[0][mt][nt][half * 2 + 0] + pb[n];
                float cp1 = c[0][mt][nt][half * 2 + 1] + pb[n + 1];
                float cq0 = c[1][mt][nt][half * 2 + 0] + qb[n];
                float cq1 = c[1][mt][nt][half * 2 + 1] + qb[n + 1];
                float cv0 = c[2][mt][nt][half * 2 + 0] + vb[n];
                float cv1 = c[2][mt][nt][half * 2 + 1] + vb[n + 1];
                float2 pv = make_float2(silu_f(cp0), silu_f(cp1));
                float qv0 = silu_f(cq0) * silu_f(cv0);
                float qv1 = silu_f(cq1) * silu_f(cv1);
                float2 qv = make_float2(__uint_as_float(to_tf32(qv0)),
                                        __uint_as_float(to_tf32(qv1)));
                *(float2*)&g_p[m * D1 + n] = pv;
                *(float2*)&g_qv[m * D1 + n] = qv;
            }
        }
    }
}

// ---------------- kernel C: axial Toeplitz + gate (TF32 mma, 4-ch blocks, no padding) ----------------
#define CH    4
#define XPL   4032    // plane: 56 rows * 72
#define XPIT  72
#define RPIT  60      // res pitch within reused X plane
#define XOFF  0
#define A1OFF (CH * XPL)             // 16128
#define A2OFF (A1OFF + CH * 128)     // 16640
#define SMEMC_FLOATS (A2OFF + CH * 128)   // 17152 floats = 68608 B

__global__ __launch_bounds__(256, 2) void toeplitz_kernel() {
    extern __shared__ float sm[];

    int dg = blockIdx.x;                    // 0..143
    int b  = blockIdx.y;                    // 0..7
    int dbase = dg * CH;
    int tid = threadIdx.x;

    for (int pos = tid; pos < HW; pos += 256) {
        float4 v = *(const float4*)&g_qv[(size_t)(b * HW + pos) * D1 + dbase];
        int i = pos / N, j = pos % N;
        int base = i * XPIT + j;
        sm[XOFF + 0 * XPL + base] = v.x;
        sm[XOFF + 1 * XPL + base] = v.y;
        sm[XOFF + 2 * XPL + base] = v.z;
        sm[XOFF + 3 * XPL + base] = v.w;
    }
    for (int idx = tid; idx < CH * 128; idx += 256) {
        int dd = idx >> 7, k = idx & 127;
        int src = (k + 49) % TWO_N;
        sm[A1OFF + idx] = g_a[src * D1 + dbase + dd];
        sm[A2OFF + idx] = g_a[TWO_N * D1 + src * D1 + dbase + dd];
    }
    __syncthreads();

    int w = tid >> 5, lane = tid & 31;
    int d = w & 3, half = w >> 2;
    int g = lane >> 2, t4 = lane & 3;
    float* X  = sm + XOFF + d * XPL;
    float* A1 = sm + A1OFF + d * 128;
    float* A2 = sm + A2OFF + d * 128;
    int M0 = half * 32;

    float C[2][7][4];
#pragma unroll
    for (int mt = 0; mt < 2; mt++)
#pragma unroll
        for (int nt = 0; nt < 7; nt++)
#pragma unroll
            for (int r = 0; r < 4; r++) C[mt][nt][r] = 0.0f;

    // ---- o1[i][j] = sum_jp X[i][jp] * a1[(j-jp) mod 112], jp = 0..55 ----
    for (int kt = 0; kt < 7; kt++) {
        int k0 = kt * 8;
        uint32_t a[2][4];
#pragma unroll
        for (int mt = 0; mt < 2; mt++) {
            int r0 = M0 + mt * 16;
            a[mt][0] = __float_as_uint(X[(r0 + g) * XPIT + k0 + t4]);
            a[mt][1] = __float_as_uint(X[(r0 + g + 8) * XPIT + k0 + t4]);
            a[mt][2] = __float_as_uint(X[(r0 + g) * XPIT + k0 + t4 + 4]);
            a[mt][3] = __float_as_uint(X[(r0 + g + 8) * XPIT + k0 + t4 + 4]);
        }
#pragma unroll
        for (int nt = 0; nt < 7; nt++) {
            int idx0 = nt * 8 + g - k0 - t4 + 63;
            uint32_t bb[2];
            bb[0] = __float_as_uint(A1[idx0]);
            bb[1] = __float_as_uint(A1[idx0 - 4]);
#pragma unroll
            for (int mt = 0; mt < 2; mt++)
                mma_tf32(C[mt][nt], a[mt], bb);
        }
    }
    // ---- o2[i][j] = sum_ip a2[(i-ip) mod 112] * X[ip][j], ip = 0..55 ----
    for (int kt = 0; kt < 7; kt++) {
        int k0 = kt * 8;
        uint32_t a[2][4];
#pragma unroll
        for (int mt = 0; mt < 2; mt++) {
            int r0 = M0 + mt * 16;
            a[mt][0] = __float_as_uint(A2[r0 + g - k0 - t4 + 63]);
            a[mt][1] = __float_as_uint(A2[r0 + g + 8 - k0 - t4 + 63]);
            a[mt][2] = __float_as_uint(A2[r0 + g - k0 - t4 - 4 + 63]);
            a[mt][3] = __float_as_uint(A2[r0 + g + 8 - k0 - t4 - 4 + 63]);
        }
#pragma unroll
        for (int nt = 0; nt < 7; nt++) {
            uint32_t bb[2];
            bb[0] = __float_as_uint(X[(k0 + t4) * XPIT + nt * 8 + g]);
            bb[1] = __float_as_uint(X[(k0 + t4 + 4) * XPIT + nt * 8 + g]);
#pragma unroll
            for (int mt = 0; mt < 2; mt++)
                mma_tf32(C[mt][nt], a[mt], bb);
        }
    }
    __syncthreads();    // all X reads done -> X planes reusable as res buffer

    {
        float* R = sm + XOFF + d * XPL;
#pragma unroll
        for (int mt = 0; mt < 2; mt++) {
            int ia = M0 + mt * 16 + g;
            int ib = ia + 8;
#pragma unroll
            for (int nt = 0; nt < 7; nt++) {
                int j = nt * 8 + 2 * t4;
                if (ia < 56) {
                    R[ia * RPIT + j]     = C[mt][nt][0];
                    R[ia * RPIT + j + 1] = C[mt][nt][1];
                }
                if (ib < 56) {
                    R[ib * RPIT + j]     = C[mt][nt][2];
                    R[ib * RPIT + j + 1] = C[mt][nt][3];
                }
            }
        }
    }
    __syncthreads();

    for (int pos = tid; pos < HW; pos += 256) {
        int ir = pos / N, j = pos % N;
        size_t gidx = (size_t)(b * HW + pos) * D1 + dbase;
        float4 pv = *(const float4*)&g_p[gidx];
        int base = ir * RPIT + j;
        float4 o;
        o.x = pv.x * sm[XOFF + 0 * XPL + base];
        o.y = pv.y * sm[XOFF + 1 * XPL + base];
        o.z = pv.z * sm[XOFF + 2 * XPL + base];
        o.w = pv.w * sm[XOFF + 3 * XPL + base];
        *(float4*)&g_t[gidx] = o;
    }
}

// ---------------- kernel D: output GEMM (TF32 mma, 2-stage pipeline, 3 blocks/SM) ----------------
#define OAPITCH 136
#define OBPITCH 72
#define OUT_SMEM ((2 * 32 * OAPITCH + 2 * 32 * OBPITCH) * 4)   // 53248 B
__global__ __launch_bounds__(256, 3) void out_gemm_kernel(
    const float* __restrict__ ow, const float* __restrict__ ob,
    float* __restrict__ out) {
    extern __shared__ float smem[];
    float (*As)[32][OAPITCH] = (float (*)[32][OAPITCH])smem;
    float (*Bs)[32][OBPITCH] = (float (*)[32][OBPITCH])(smem + 2 * 32 * OAPITCH);

    int tid = threadIdx.x;
    int warp = tid >> 5, lane = tid & 31;
    int wm = (warp >> 1) * 32;
    int wn = (warp & 1) * 32;
    int quad = lane >> 2, tid4 = lane & 3;
    int m0 = blockIdx.y * 128, n0 = blockIdx.x * 64;

    int lrow = tid >> 1;
    int lcb  = (tid & 1) * 16;
    int wrow = tid >> 2;
    int wkb  = (tid & 3) * 8;

    float c[2][4][4];
#pragma unroll
    for (int i = 0; i < 2; i++)
#pragma unroll
        for (int j = 0; j < 4; j++)
#pragma unroll
            for (int r = 0; r < 4; r++) c[i][j][r] = 0.0f;

    float4 pa[4];
    float4 pb2[2];

#pragma unroll
    for (int v = 0; v < 4; v++)
        pa[v] = *(const float4*)&g_t[(size_t)(m0 + lrow) * D1 + lcb + v * 4];
    pb2[0] = *(const float4*)&ow[(n0 + wrow) * D1 + wkb];
    pb2[1] = *(const float4*)&ow[(n0 + wrow) * D1 + wkb + 4];
    {
#pragma unroll
        for (int v = 0; v < 4; v++) {
            As[0][lcb + v * 4 + 0][lrow] = __uint_as_float(to_tf32(pa[v].x));
            As[0][lcb + v * 4 + 1][lrow] = __uint_as_float(to_tf32(pa[v].y));
            As[0][lcb + v * 4 + 2][lrow] = __uint_as_float(to_tf32(pa[v].z));
            As[0][lcb + v * 4 + 3][lrow] = __uint_as_float(to_tf32(pa[v].w));
        }
        Bs[0][wkb + 0][wrow] = __uint_as_float(to_tf32(pb2[0].x));
        Bs[0][wkb + 1][wrow] = __uint_as_float(to_tf32(pb2[0].y));
        Bs[0][wkb + 2][wrow] = __uint_as_float(to_tf32(pb2[0].z));
        Bs[0][wkb + 3][wrow] = __uint_as_float(to_tf32(pb2[0].w));
        Bs[0][wkb + 4][wrow] = __uint_as_float(to_tf32(pb2[1].x));
        Bs[0][wkb + 5][wrow] = __uint_as_float(to_tf32(pb2[1].y));
        Bs[0][wkb + 6][wrow] = __uint_as_float(to_tf32(pb2[1].z));
        Bs[0][wkb + 7][wrow] = __uint_as_float(to_tf32(pb2[1].w));
    }
    __syncthreads();

    int s = 0;
    for (int kb = 0; kb < D1; kb += 32, s ^= 1) {
        bool hasNext = (kb + 32) < D1;
        if (hasNext) {
            int kn = kb + 32;
#pragma unroll
            for (int v = 0; v < 4; v++)
                pa[v] = *(const float4*)&g_t[(size_t)(m0 + lrow) * D1 + kn + lcb + v * 4];
            pb2[0] = *(const float4*)&ow[(n0 + wrow) * D1 + kn + wkb];
            pb2[1] = *(const float4*)&ow[(n0 + wrow) * D1 + kn + wkb + 4];
        }

#pragma unroll
        for (int k8 = 0; k8 < 32; k8 += 8) {
            uint32_t a[2][4];
#pragma unroll
            for (int mt = 0; mt < 2; mt++) {
                int mb = wm + mt * 16;
                a[mt][0] = __float_as_uint(As[s][k8 + tid4][mb + quad]);
                a[mt][1] = __float_as_uint(As[s][k8 + tid4][mb + quad + 8]);
                a[mt][2] = __float_as_uint(As[s][k8 + tid4 + 4][mb + quad]);
                a[mt][3] = __float_as_uint(As[s][k8 + tid4 + 4][mb + quad + 8]);
            }
#pragma unroll
            for (int nt = 0; nt < 4; nt++) {
                uint32_t b[2];
                int nb = wn + nt * 8 + quad;
                b[0] = __float_as_uint(Bs[s][k8 + tid4][nb]);
                b[1] = __float_as_uint(Bs[s][k8 + tid4 + 4][nb]);
#pragma unroll
                for (int mt = 0; mt < 2; mt++)
                    mma_tf32(c[mt][nt], a[mt], b);
            }
        }

        if (hasNext) {
            int ns = s ^ 1;
#pragma unroll
            for (int v = 0; v < 4; v++) {
                As[ns][lcb + v * 4 + 0][lrow] = __uint_as_float(to_tf32(pa[v].x));
                As[ns][lcb + v * 4 + 1][lrow] = __uint_as_float(to_tf32(pa[v].y));
                As[ns][lcb + v * 4 + 2][lrow] = __uint_as_float(to_tf32(pa[v].z));
                As[ns][lcb + v * 4 + 3][lrow] = __uint_as_float(to_tf32(pa[v].w));
            }
            Bs[ns][wkb + 0][wrow] = __uint_as_float(to_tf32(pb2[0].x));
            Bs[ns][wkb + 1][wrow] = __uint_as_float(to_tf32(pb2[0].y));
            Bs[ns][wkb + 2][wrow] = __uint_as_float(to_tf32(pb2[0].z));
            Bs[ns][wkb + 3][wrow] = __uint_as_float(to_tf32(pb2[0].w));
            Bs[ns][wkb + 4][wrow] = __uint_as_float(to_tf32(pb2[1].x));
            Bs[ns][wkb + 5][wrow] = __uint_as_float(to_tf32(pb2[1].y));
            Bs[ns][wkb + 6][wrow] = __uint_as_float(to_tf32(pb2[1].z));
            Bs[ns][wkb + 7][wrow] = __uint_as_float(to_tf32(pb2[1].w));
        }
        __syncthreads();
    }

#pragma unroll
    for (int mt = 0; mt < 2; mt++) {
#pragma unroll
        for (int half = 0; half < 2; half++) {
            int m = m0 + wm + mt * 16 + quad + half * 8;
#pragma unroll
            for (int nt = 0; nt < 4; nt++) {
                int n = n0 + wn + nt * 8 + tid4 * 2;
                float2 o = make_float2(c[mt][nt][half * 2 + 0] + ob[n],
                                       c[mt][nt][half * 2 + 1] + ob[n + 1]);
                *(float2*)&out[m * EMBED + n] = o;
            }
        }
    }
}

// ---------------- launch ----------------
extern "C" void kernel_launch(void* const* d_in, const int* in_sizes, int n_in,
                              void* d_out, int out_size) {
    const float* x    = (const float*)d_in[0];
    const float* p_w  = (const float*)d_in[1];
    const float* p_b  = (const float*)d_in[2];
    const float* q_w  = (const float*)d_in[3];
    const float* q_b  = (const float*)d_in[4];
    const float* v_w  = (const float*)d_in[5];
    const float* v_b  = (const float*)d_in[6];
    const float* o_w  = (const float*)d_in[7];
    const float* o_b  = (const float*)d_in[8];
    const float* slope = (const float*)d_in[9];
    const float* t1_w0 = (const float*)d_in[10];
    const float* t1_b0 = (const float*)d_in[11];
    const float* t1_ws = (const float*)d_in[12];
    const float* t1_bs = (const float*)d_in[13];
    const float* t1_wo = (const float*)d_in[14];
    const float* t1_bo = (const float*)d_in[15];
    const float* t2_w0 = (const float*)d_in[16];
    const float* t2_b0 = (const float*)d_in[17];
    const float* t2_ws = (const float*)d_in[18];
    const float* t2_bs = (const float*)d_in[19];
    const float* t2_wo = (const float*)d_in[20];
    const float* t2_bo = (const float*)d_in[21];
    float* out = (float*)d_out;

    static const int smemC = SMEMC_FLOATS * (int)sizeof(float);   // 68608 B
    cudaFuncSetAttribute(toeplitz_kernel, cudaFuncAttributeMaxDynamicSharedMemorySize, smemC);
    cudaFuncSetAttribute(pqv_kernel, cudaFuncAttributeMaxDynamicSharedMemorySize, PQV_SMEM);
    cudaFuncSetAttribute(out_gemm_kernel, cudaFuncAttributeMaxDynamicSharedMemorySize, OUT_SMEM);

    rpe_kernel<<<2 * TWO_N, 128>>>(t1_w0, t1_b0, t1_ws, t1_bs, t1_wo, t1_bo,
                                   t2_w0, t2_b0, t2_ws, t2_bs, t2_wo, t2_bo, slope);
    pqv_kernel<<<dim3(D1 / 32, TOK / 128), 256, PQV_SMEM>>>(x, p_w, p_b, q_w, q_b, v_w, v_b);
    toeplitz_kernel<<<dim3(D1 / CH, B), 256, smemC>>>();
    out_gemm_kernel<<<dim3(EMBED / 64, TOK / 128), 256, OUT_SMEM>>>(o_w, o_b, out);
}